// round 13
// baseline (speedup 1.0000x reference)
#include <cuda_runtime.h>
#include <math.h>

// Problem constants
#define BB 128
#define CC 768
#define NN 196
#define DD 128
#define TK 8
#define NC 16                      // candidate count for exact re-rank
#define M_NODES (BB * NN)          // 25088
#define NE      (M_NODES * TK)     // 200704

typedef unsigned long long u64;
typedef unsigned int u32;

// Scratch (device globals; no allocations allowed)
__device__ float  g_nrm[M_NODES * DD];          // normalized nodes (fp32, candidate stage)
__device__ float  g_sim[BB * NN * NN];          // similarity (fp32, candidate stage)
__device__ double g_dinv[M_NODES];              // double 1/||node||
__device__ int    g_cand[M_NODES * NC];         // top-16 fp32 candidates
__device__ int    g_adj[NE];                    // final top-8 indices
__device__ float  g_table[27 * 27 * DD];        // pos-MLP table
__device__ float  g_c1[M_NODES * DD];           // nodes @ We1[0:128]
__device__ float  g_c2[M_NODES * DD];           // nodes @ We1[128:256]
__device__ float  g_c3[27 * 27 * DD];           // table @ We1[256:384] + be1

__device__ __forceinline__ float gelu_exact(float x) {
    return 0.5f * x * (1.0f + erff(x * 0.70710678118654752440f));
}
__device__ __forceinline__ double gelu_exact_d(double x) {
    return 0.5 * x * (1.0 + erf(x * 0.7071067811865475244));
}

// ---- packed f32x2 helpers (used by sim kernel; IEEE per-lane) ----
__device__ __forceinline__ u64 pack2(float x) {
    unsigned int u = __float_as_uint(x);
    u64 r;
    asm("mov.b64 %0, {%1, %1};" : "=l"(r) : "r"(u));
    return r;
}
__device__ __forceinline__ void fma2(u64& d, u64 a, u64 b) {
    asm("fma.rn.f32x2 %0, %1, %2, %0;" : "+l"(d) : "l"(a), "l"(b));
}
__device__ __forceinline__ float2 unpack2(u64 v) {
    unsigned int lo, hi;
    asm("mov.b64 {%0, %1}, %2;" : "=r"(lo), "=r"(hi) : "l"(v));
    return make_float2(__uint_as_float(lo), __uint_as_float(hi));
}

// ---- tf32 helpers ----
__device__ __forceinline__ void split_tf32(float x, u32& hi, u32& lo) {
    asm("cvt.rna.tf32.f32 %0, %1;" : "=r"(hi) : "f"(x));
    float r = x - __uint_as_float(hi);
    asm("cvt.rna.tf32.f32 %0, %1;" : "=r"(lo) : "f"(r));
}
__device__ __forceinline__ void mma_tf32(float* d, u32 a0, u32 a1, u32 a2, u32 a3,
                                         u32 b0, u32 b1) {
    asm volatile(
        "mma.sync.aligned.m16n8k8.row.col.f32.tf32.tf32.f32 "
        "{%0,%1,%2,%3}, {%4,%5,%6,%7}, {%8,%9}, {%0,%1,%2,%3};"
        : "+f"(d[0]), "+f"(d[1]), "+f"(d[2]), "+f"(d[3])
        : "r"(a0), "r"(a1), "r"(a2), "r"(a3), "r"(b0), "r"(b1));
}

// ---------------------------------------------------------------------------
// Kernel 1: pos-MLP table. disp has only 27x27 distinct values (i/13 grid).
// ---------------------------------------------------------------------------
__global__ void pos_table_kernel(const float* __restrict__ Wp1, const float* __restrict__ bp1,
                                 const float* __restrict__ Wp2, const float* __restrict__ bp2) {
    __shared__ float h[64];
    int idx = blockIdx.x;
    float dy = (float)(idx / 27 - 13) * (1.0f / 13.0f);
    float dx = (float)(idx % 27 - 13) * (1.0f / 13.0f);
    int t = threadIdx.x;
    if (t < 64) {
        float v = dy * Wp1[t] + dx * Wp1[64 + t] + bp1[t];
        h[t] = gelu_exact(v);
    }
    __syncthreads();
    float acc = bp2[t];
    #pragma unroll 8
    for (int i = 0; i < 64; i++) acc += h[i] * Wp2[i * DD + t];
    g_table[idx * DD + t] = acc;
}

// ---------------------------------------------------------------------------
// Kernel 2: nodes = GELU(LN(tokens @ W_node + b_node)), fused L2-normalize.
// 32-row tile, 256 threads, 4x4 micro. Chunked-double accumulation.
// (r11 best-measured version, unchanged.)
// ---------------------------------------------------------------------------
__global__ void node_kernel(const float* __restrict__ feat, const float* __restrict__ Wn,
                            const float* __restrict__ bnode, const float* __restrict__ ln_g,
                            const float* __restrict__ ln_b, float* __restrict__ nodes_out) {
    __shared__ float As[16][36];
    __shared__ float4 Bs[16 * 32];
    __shared__ float Cs[32][132];
    __shared__ int s_base[32];
    int tid = threadIdx.x;
    int m0 = blockIdx.x * 32;
    if (tid < 32) {
        int m = m0 + tid;
        int b = m / NN, n = m % NN;
        s_base[tid] = b * (CC * NN) + n;
    }
    int tx = tid & 31, ty = tid >> 5;
    double dacc[4][4];
    #pragma unroll
    for (int i = 0; i < 4; i++)
        #pragma unroll
        for (int q = 0; q < 4; q++) dacc[i][q] = 0.0;
    float acc[4][4] = {};
    int cnt = 0;
    __syncthreads();
    for (int k0 = 0; k0 < CC; k0 += 16) {
        #pragma unroll
        for (int i = 0; i < 2; i++) {
            int e = tid + i * 256;
            int r = e & 31, cc = e >> 5;
            As[cc][r] = feat[s_base[r] + (k0 + cc) * NN];
        }
        const float4* Wg = (const float4*)(Wn + k0 * DD);
        Bs[tid] = Wg[tid];
        Bs[tid + 256] = Wg[tid + 256];
        __syncthreads();
        #pragma unroll
        for (int cc = 0; cc < 16; cc++) {
            float4 bv = Bs[cc * 32 + tx];
            float4 a = *(float4*)&As[cc][ty * 4];
            float av[4] = {a.x, a.y, a.z, a.w};
            #pragma unroll
            for (int i = 0; i < 4; i++) {
                acc[i][0] += av[i] * bv.x; acc[i][1] += av[i] * bv.y;
                acc[i][2] += av[i] * bv.z; acc[i][3] += av[i] * bv.w;
            }
        }
        if (++cnt == 3) {
            cnt = 0;
            #pragma unroll
            for (int i = 0; i < 4; i++)
                #pragma unroll
                for (int q = 0; q < 4; q++) {
                    dacc[i][q] += (double)acc[i][q];
                    acc[i][q] = 0.f;
                }
        }
        __syncthreads();
    }
    float4 bb = ((const float4*)bnode)[tx];
    #pragma unroll
    for (int i = 0; i < 4; i++) {
        int r = ty * 4 + i;
        *(float4*)&Cs[r][tx * 4] = make_float4(
            (float)(dacc[i][0] + (double)bb.x), (float)(dacc[i][1] + (double)bb.y),
            (float)(dacc[i][2] + (double)bb.z), (float)(dacc[i][3] + (double)bb.w));
    }
    __syncthreads();
    int lane = tx, w = ty;
    for (int rr = 0; rr < 4; rr++) {
        int r = w + 8 * rr;
        double x[4];
        double s = 0.0;
        #pragma unroll
        for (int q = 0; q < 4; q++) { x[q] = (double)Cs[r][lane + 32 * q]; s += x[q]; }
        #pragma unroll
        for (int o = 16; o > 0; o >>= 1) s += __shfl_xor_sync(~0u, s, o);
        double mu = s * (1.0 / 128.0);
        double vs = 0.0;
        #pragma unroll
        for (int q = 0; q < 4; q++) { double d = x[q] - mu; vs += d * d; }
        #pragma unroll
        for (int o = 16; o > 0; o >>= 1) vs += __shfl_xor_sync(~0u, vs, o);
        double rs = 1.0 / sqrt(vs * (1.0 / 128.0) + 1e-5);
        int row = m0 + r;
        float yf[4];
        double ssd = 0.0;
        #pragma unroll
        for (int q = 0; q < 4; q++) {
            int d = lane + 32 * q;
            double y = (x[q] - mu) * rs * (double)ln_g[d] + (double)ln_b[d];
            yf[q] = (float)gelu_exact_d(y);
            nodes_out[(size_t)row * DD + d] = yf[q];
            ssd += (double)yf[q] * yf[q];
        }
        #pragma unroll
        for (int o = 16; o > 0; o >>= 1) ssd += __shfl_xor_sync(~0u, ssd, o);
        double dinv = 1.0 / fmax(sqrt(ssd), 1e-12);
        if (lane == 0) g_dinv[row] = dinv;
        float inv = (float)dinv;
        #pragma unroll
        for (int q = 0; q < 4; q++)
            g_nrm[(size_t)row * DD + lane + 32 * q] = yf[q] * inv;
    }
}

// ---------------------------------------------------------------------------
// Kernel 4: sim = nrm @ nrm^T per batch. 32x32 tile, 64 threads, 4x4 micro,
// f32x2 packed FMA.
// ---------------------------------------------------------------------------
__global__ void sim_kernel() {
    __shared__ float As[32][36];
    __shared__ float Bs[32][36];
    int tid = threadIdx.x;
    const float* base = g_nrm + (size_t)blockIdx.z * (NN * DD);
    int by = blockIdx.y, bx = blockIdx.x;
    int tx = tid & 7, ty = tid >> 3;
    u64 acc2[2][4] = {};
    for (int k0 = 0; k0 < 128; k0 += 32) {
        #pragma unroll
        for (int it = 0; it < 4; it++) {
            int idx = tid + it * 64;
            int r = idx >> 3, kg = (idx & 7) * 4;
            int na = by * 32 + r;
            float4 v = (na < NN) ? *(const float4*)(base + (size_t)na * DD + k0 + kg)
                                 : make_float4(0.f, 0.f, 0.f, 0.f);
            As[kg + 0][r] = v.x; As[kg + 1][r] = v.y; As[kg + 2][r] = v.z; As[kg + 3][r] = v.w;
            int ma = bx * 32 + r;
            float4 u = (ma < NN) ? *(const float4*)(base + (size_t)ma * DD + k0 + kg)
                                 : make_float4(0.f, 0.f, 0.f, 0.f);
            Bs[kg + 0][r] = u.x; Bs[kg + 1][r] = u.y; Bs[kg + 2][r] = u.z; Bs[kg + 3][r] = u.w;
        }
        __syncthreads();
        #pragma unroll
        for (int k = 0; k < 32; k++) {
            ulonglong2 av = *(const ulonglong2*)&As[k][ty * 4];
            u64 ap[2] = {av.x, av.y};
            float4 b = *(float4*)&Bs[k][tx * 4];
            u64 b2[4] = {pack2(b.x), pack2(b.y), pack2(b.z), pack2(b.w)};
            #pragma unroll
            for (int p = 0; p < 2; p++)
                #pragma unroll
                for (int j = 0; j < 4; j++) fma2(acc2[p][j], ap[p], b2[j]);
        }
        __syncthreads();
    }
    float accf[4][4];
    #pragma unroll
    for (int p = 0; p < 2; p++)
        #pragma unroll
        for (int j = 0; j < 4; j++) {
            float2 v = unpack2(acc2[p][j]);
            accf[2 * p][j] = v.x;
            accf[2 * p + 1][j] = v.y;
        }
    float* simb = g_sim + (size_t)blockIdx.z * (NN * NN);
    #pragma unroll
    for (int i = 0; i < 4; i++) {
        int n0 = by * 32 + ty * 4 + i;
        if (n0 >= NN) break;
        int mcol = bx * 32 + tx * 4;
        if (mcol + 3 < NN) {
            *(float4*)(simb + n0 * NN + mcol) =
                make_float4(accf[i][0], accf[i][1], accf[i][2], accf[i][3]);
        } else {
            #pragma unroll
            for (int j = 0; j < 4; j++)
                if (mcol + j < NN) simb[n0 * NN + mcol + j] = accf[i][j];
        }
    }
}

// ---------------------------------------------------------------------------
// Kernel 5a: top-16 candidates, one WARP per row (register sort + warp argmax).
// ---------------------------------------------------------------------------
__global__ void cand_kernel() {
    int w = (blockIdx.x * blockDim.x + threadIdx.x) >> 5;
    int lane = threadIdx.x & 31;
    if (w >= M_NODES) return;
    int b = w / NN, n = w % NN;
    const float* row = g_sim + (size_t)b * (NN * NN) + n * NN;

    float v0, v1, v2, v3, v4, v5, v6;
    int   i0, i1, i2, i3, i4, i5, i6;
    {
        int m;
        m = lane;        i0 = m; v0 = (m != n) ? row[m] : -1e38f;
        m = lane + 32;   i1 = m; v1 = (m != n) ? row[m] : -1e38f;
        m = lane + 64;   i2 = m; v2 = (m != n) ? row[m] : -1e38f;
        m = lane + 96;   i3 = m; v3 = (m != n) ? row[m] : -1e38f;
        m = lane + 128;  i4 = m; v4 = (m != n) ? row[m] : -1e38f;
        m = lane + 160;  i5 = m; v5 = (m != n) ? row[m] : -1e38f;
        m = lane + 192;  i6 = m; v6 = (m < NN && m != n) ? row[m] : -1e38f;
    }
    #define CSWP(va, ia, vb, ib)                                             \
        { bool sw = (va < vb) || (va == vb && ia > ib);                      \
          float tv = sw ? vb : va; vb = sw ? va : vb; va = tv;               \
          int ti = sw ? ib : ia;   ib = sw ? ia : ib; ia = ti; }
    #pragma unroll
    for (int rnd = 0; rnd < 4; rnd++) {
        CSWP(v0, i0, v1, i1); CSWP(v2, i2, v3, i3); CSWP(v4, i4, v5, i5);
        if (rnd < 3) { CSWP(v1, i1, v2, i2); CSWP(v3, i3, v4, i4); CSWP(v5, i5, v6, i6); }
    }
    #undef CSWP

    int res = 0;
    #pragma unroll
    for (int k = 0; k < NC; k++) {
        float bv = v0; int bi = i0, bl = lane;
        #pragma unroll
        for (int o = 16; o > 0; o >>= 1) {
            float ov = __shfl_xor_sync(~0u, bv, o);
            int   oi = __shfl_xor_sync(~0u, bi, o);
            int   ol = __shfl_xor_sync(~0u, bl, o);
            bool take = (ov > bv) || (ov == bv && oi < bi);
            bv = take ? ov : bv; bi = take ? oi : bi; bl = take ? ol : bl;
        }
        if (lane == bl) {
            v0 = v1; i0 = i1; v1 = v2; i1 = i2; v2 = v3; i2 = i3;
            v3 = v4; i3 = i4; v4 = v5; i4 = i5; v5 = v6; i5 = i6;
            v6 = -1e38f;
        }
        if (lane == k) res = bi;
    }
    if (lane < NC) g_cand[w * NC + lane] = res;
}

// ---------------------------------------------------------------------------
// Kernel 5b: exact re-rank in double; fp32 round; stable sort; emit top-8.
// ---------------------------------------------------------------------------
__global__ void refine_kernel(const float* __restrict__ nodes, float* __restrict__ adj_out) {
    __shared__ float skey[8][NC];
    __shared__ int   sidx[8][NC];
    int wip = threadIdx.x >> 5;
    int lane = threadIdx.x & 31;
    int t = blockIdx.x * 8 + wip;
    if (t >= M_NODES) return;
    int b = t / NN;
    int rowbase = b * NN;
    double dinv_n = g_dinv[t];
    float4 av = ((const float4*)(nodes + (size_t)t * DD))[lane];
    int myc = (lane < NC) ? g_cand[t * NC + lane] : 0;
    #pragma unroll
    for (int c = 0; c < NC; c++) {
        int j = __shfl_sync(~0u, myc, c);
        float4 bv = ((const float4*)(nodes + (size_t)(rowbase + j) * DD))[lane];
        double p = (double)av.x * bv.x + (double)av.y * bv.y
                 + (double)av.z * bv.z + (double)av.w * bv.w;
        #pragma unroll
        for (int o = 16; o > 0; o >>= 1) p += __shfl_xor_sync(~0u, p, o);
        if (lane == c) {
            double sim = p * dinv_n * g_dinv[rowbase + j];
            skey[wip][c] = (float)sim;
            sidx[wip][c] = j;
        }
    }
    __syncwarp();
    if (lane == 0) {
        float kv[NC]; int ki[NC];
        #pragma unroll
        for (int i = 0; i < NC; i++) { kv[i] = skey[wip][i]; ki[i] = sidx[wip][i]; }
        #pragma unroll
        for (int i = 1; i < NC; i++) {
            float v = kv[i]; int id = ki[i];
            int p = i - 1;
            while (p >= 0 && (kv[p] < v || (kv[p] == v && ki[p] > id))) {
                kv[p + 1] = kv[p]; ki[p + 1] = ki[p]; p--;
            }
            kv[p + 1] = v; ki[p + 1] = id;
        }
        #pragma unroll
        for (int k = 0; k < TK; k++) {
            g_adj[t * TK + k] = ki[k];
            adj_out[t * TK + k] = (float)ki[k];
        }
    }
}

// ---------------------------------------------------------------------------
// Kernel 6: C{1,2} = nodes @ We1[seg*128 : seg*128+128].
// 64x128 tile, 256 threads, 8x4 micro, scalar FFMA.
// ---------------------------------------------------------------------------
__global__ void cgemm64_kernel(const float* __restrict__ nodes, const float* __restrict__ We1) {
    __shared__ float As[32][68];
    __shared__ float4 Bs[1024];
    int tid = threadIdx.x;
    int m0 = blockIdx.x * 64;
    int seg = blockIdx.y;
    float* C = seg ? g_c2 : g_c1;
    const float* W = We1 + (size_t)seg * 128 * DD;
    int tx = tid & 31, ty = tid >> 5;
    float acc[8][4] = {};
    for (int k0 = 0; k0 < 128; k0 += 32) {
        {
            int r = tid >> 2, cb = (tid & 3) * 8;
            const float4* p = (const float4*)(nodes + (size_t)(m0 + r) * DD + k0 + cb);
            float4 v0 = p[0], v1 = p[1];
            As[cb + 0][r] = v0.x; As[cb + 1][r] = v0.y; As[cb + 2][r] = v0.z; As[cb + 3][r] = v0.w;
            As[cb + 4][r] = v1.x; As[cb + 5][r] = v1.y; As[cb + 6][r] = v1.z; As[cb + 7][r] = v1.w;
        }
        {
            const float4* Wg = (const float4*)(W + k0 * DD);
            #pragma unroll
            for (int i = 0; i < 4; i++) Bs[tid + i * 256] = Wg[tid + i * 256];
        }
        __syncthreads();
        #pragma unroll
        for (int cc = 0; cc < 32; cc++) {
            float4 bv = Bs[cc * 32 + tx];
            float4 a0 = *(float4*)&As[cc][ty * 8];
            float4 a1 = *(float4*)&As[cc][ty * 8 + 4];
            float ar[8] = {a0.x, a0.y, a0.z, a0.w, a1.x, a1.y, a1.z, a1.w};
            #pragma unroll
            for (int i = 0; i < 8; i++) {
                acc[i][0] += ar[i] * bv.x; acc[i][1] += ar[i] * bv.y;
                acc[i][2] += ar[i] * bv.z; acc[i][3] += ar[i] * bv.w;
            }
        }
        __syncthreads();
    }
    #pragma unroll
    for (int i = 0; i < 8; i++) {
        int row = m0 + ty * 8 + i;
        ((float4*)(C + (size_t)row * DD))[tx] =
            make_float4(acc[i][0], acc[i][1], acc[i][2], acc[i][3]);
    }
}

// ---------------------------------------------------------------------------
// Kernel 7: C3 = table @ We1[256:384] + be1 (729 rows, tiny).
// ---------------------------------------------------------------------------
__global__ void c3_kernel(const float* __restrict__ We1, const float* __restrict__ be1) {
    __shared__ float ts[128];
    int row = blockIdx.x, t = threadIdx.x;
    ts[t] = g_table[row * DD + t];
    __syncthreads();
    float acc = be1[t];
    const float* W = We1 + (size_t)256 * DD;
    #pragma unroll 8
    for (int k = 0; k < 128; k++) acc += ts[k] * W[k * DD + t];
    g_c3[row * DD + t] = acc;
}

// ---------------------------------------------------------------------------
// Kernel 8 (NEW): edges = GELU(C1[n]+C2[adj]+C3[disp]) @ We2 + be2 via
// tensor cores: mma.m16n8k8 tf32 with 3-term hi/lo split (~fp32 accuracy).
// Block = 256 thr (8 warps), tile 128 rows x 128 cols, K chunked by 32.
// Warp w computes rows 16w..16w+15, all 128 cols (16 n-tiles).
// smem layouts padded for conflict-free fragment loads:
//   A[row][k] pad 36  -> bank = 4*group + tig (distinct)
//   B[k][n]  pad 136 -> bank = 8*tig + group (distinct)
// ---------------------------------------------------------------------------
#define ET_UINTS (2 * 32 * 136 + 2 * 128 * 36)   // B hi/lo + A hi/lo
#define ET_SMEM  (ET_UINTS * 4)                  // 71680 bytes

__global__ void edge_tensor_kernel(const float* __restrict__ We2,
                                   const float* __restrict__ be2,
                                   float* __restrict__ edges_out) {
    extern __shared__ u32 usm[];
    u32* Bhi = usm;                      // [32][136]
    u32* Blo = Bhi + 32 * 136;
    u32* Ahi = Blo + 32 * 136;           // [128][36]
    u32* Alo = Ahi + 128 * 36;
    __shared__ int s1[128], s2[128], s3[128];
    __shared__ float sbias[128];
    int tid = threadIdx.x;
    int m0 = blockIdx.x * 128;
    if (tid < 128) {
        int e = m0 + tid;
        int bn = e >> 3;
        int b = bn / NN, n = bn - b * NN;
        int j = g_adj[e];
        s1[tid] = bn * DD;
        s2[tid] = (b * NN + j) * DD;
        int rn = n / 14, cn = n % 14, rj = j / 14, cj = j % 14;
        s3[tid] = ((rj - rn + 13) * 27 + (cj - cn + 13)) * DD;
        sbias[tid] = be2[tid];
    }
    __syncthreads();

    int lane = tid & 31, wid = tid >> 5;
    int g = lane >> 2, tig = lane & 3;
    int wr0 = wid * 16;

    float acc[16][4];
    #pragma unroll
    for (int nt = 0; nt < 16; nt++)
        #pragma unroll
        for (int i = 0; i < 4; i++) acc[nt][i] = 0.f;

    for (int kc = 0; kc < 4; kc++) {
        int k0 = kc * 32;
        // stage + convert B chunk (We2[k0:k0+32][0:128])
        {
            int k = tid >> 3, nb = (tid & 7) * 16;
            const float4* src = (const float4*)(We2 + (size_t)(k0 + k) * DD + nb);
            #pragma unroll
            for (int q = 0; q < 4; q++) {
                float4 v = src[q];
                int base = k * 136 + nb + q * 4;
                split_tf32(v.x, Bhi[base + 0], Blo[base + 0]);
                split_tf32(v.y, Bhi[base + 1], Blo[base + 1]);
                split_tf32(v.z, Bhi[base + 2], Blo[base + 2]);
                split_tf32(v.w, Bhi[base + 3], Blo[base + 3]);
            }
        }
        // stage + convert A chunk: gather + GELU (exact fp32), then split
        {
            int r = tid >> 1, ks = (tid & 1) * 16;
            const float* p1 = g_c1 + s1[r] + k0 + ks;
            const float* p2 = g_c2 + s2[r] + k0 + ks;
            const float* p3 = g_c3 + s3[r] + k0 + ks;
            #pragma unroll
            for (int q = 0; q < 4; q++) {
                float4 v1 = *(const float4*)(p1 + q * 4);
                float4 v2 = *(const float4*)(p2 + q * 4);
                float4 v3 = *(const float4*)(p3 + q * 4);
                int base = r * 36 + ks + q * 4;
                split_tf32(gelu_exact(v1.x + v2.x + v3.x), Ahi[base + 0], Alo[base + 0]);
                split_tf32(gelu_exact(v1.y + v2.y + v3.y), Ahi[base + 1], Alo[base + 1]);
                split_tf32(gelu_exact(v1.z + v2.z + v3.z), Ahi[base + 2], Alo[base + 2]);
                split_tf32(gelu_exact(v1.w + v2.w + v3.w), Ahi[base + 3], Alo[base + 3]);
            }
        }
        __syncthreads();
        #pragma unroll
        for (int kk = 0; kk < 4; kk++) {
            int k8 = kk * 8;
            int ra = (wr0 + g) * 36 + k8 + tig;
            int rb = (wr0 + g + 8) * 36 + k8 + tig;
            u32 ah0 = Ahi[ra],     ah1 = Ahi[rb];
            u32 ah2 = Ahi[ra + 4], ah3 = Ahi[rb + 4];
            u32 al0 = Alo[ra],     al1 = Alo[rb];
            u32 al2 = Alo[ra + 4], al3 = Alo[rb + 4];
            #pragma unroll
            for (int nt = 0; nt < 16; nt++) {
                int nc = nt * 8 + g;
                int kb0 = (k8 + tig) * 136 + nc;
                int kb1 = (k8 + tig + 4) * 136 + nc;
                u32 bh0 = Bhi[kb0], bh1 = Bhi[kb1];
                u32 bl0 = Blo[kb0], bl1 = Blo[kb1];
                mma_tf32(acc[nt], al0, al1, al2, al3, bh0, bh1);   // Alo*Bhi
                mma_tf32(acc[nt], ah0, ah1, ah2, ah3, bl0, bl1);   // Ahi*Blo
                mma_tf32(acc[nt], ah0, ah1, ah2, ah3, bh0, bh1);   // Ahi*Bhi
            }
        }
        __syncthreads();
    }

    // epilogue: c0,c1 -> (row g, cols 2tig,2tig+1); c2,c3 -> row g+8
    #pragma unroll
    for (int nt = 0; nt < 16; nt++) {
        int col = nt * 8 + 2 * tig;
        float bx = sbias[col], by = sbias[col + 1];
        int r0 = m0 + wr0 + g;
        *(float2*)(edges_out + (size_t)r0 * DD + col) =
            make_float2(acc[nt][0] + bx, acc[nt][1] + by);
        *(float2*)(edges_out + (size_t)(r0 + 8) * DD + col) =
            make_float2(acc[nt][2] + bx, acc[nt][3] + by);
    }
}

// ---------------------------------------------------------------------------
extern "C" void kernel_launch(void* const* d_in, const int* in_sizes, int n_in,
                              void* d_out, int out_size) {
    const float* feat = (const float*)d_in[0];
    const float* Wn   = (const float*)d_in[1];
    const float* bn   = (const float*)d_in[2];
    const float* lng  = (const float*)d_in[3];
    const float* lnb  = (const float*)d_in[4];
    const float* Wp1  = (const float*)d_in[5];
    const float* bp1  = (const float*)d_in[6];
    const float* Wp2  = (const float*)d_in[7];
    const float* bp2  = (const float*)d_in[8];
    const float* We1  = (const float*)d_in[9];
    const float* be1  = (const float*)d_in[10];
    const float* We2  = (const float*)d_in[11];
    const float* be2  = (const float*)d_in[12];

    float* out = (float*)d_out;
    float* nodes_out = out;                                   // B*N*D
    float* edges_out = out + (size_t)M_NODES * DD;            // B*N*K*D
    float* adj_out   = edges_out + (size_t)NE * DD;           // B*N*K

    static int s_attr_done = 0;
    if (!s_attr_done) {
        cudaFuncSetAttribute(edge_tensor_kernel,
                             cudaFuncAttributeMaxDynamicSharedMemorySize, ET_SMEM);
        s_attr_done = 1;
    }

    pos_table_kernel<<<729, 128>>>(Wp1, bp1, Wp2, bp2);
    node_kernel<<<M_NODES / 32, 256>>>(feat, Wn, bn, lng, lnb, nodes_out);
    sim_kernel<<<dim3(7, 7, BB), 64>>>();
    cand_kernel<<<(M_NODES * 32 + 255) / 256, 256>>>();
    refine_kernel<<<(M_NODES + 7) / 8, 256>>>(nodes_out, adj_out);
    cgemm64_kernel<<<dim3(M_NODES / 64, 2), 256>>>(nodes_out, We1);
    c3_kernel<<<729, 128>>>(We1, be1);
    edge_tensor_kernel<<<NE / 128, 256, ET_SMEM>>>(We2, be2, edges_out);
}

// round 14
// speedup vs baseline: 1.0291x; 1.0291x over previous
#include <cuda_runtime.h>
#include <math.h>

// Problem constants
#define BB 128
#define CC 768
#define NN 196
#define DD 128
#define TK 8
#define NC 16                      // candidate count for exact re-rank
#define M_NODES (BB * NN)          // 25088
#define NE      (M_NODES * TK)     // 200704

typedef unsigned long long u64;

// Scratch (device globals; no allocations allowed)
__device__ float  g_nrm[M_NODES * DD];          // normalized nodes (fp32, candidate stage)
__device__ float  g_sim[BB * NN * NN];          // similarity (fp32, candidate stage)
__device__ double g_dinv[M_NODES];              // double 1/||node||
__device__ int    g_cand[M_NODES * NC];         // top-16 fp32 candidates
__device__ int    g_adj[NE];                    // final top-8 indices
__device__ float  g_posh[729 * 64];             // pos-MLP hidden layer
__device__ float  g_table[27 * 27 * DD];        // pos-MLP table
__device__ float  g_c1[M_NODES * DD];           // nodes @ We1[0:128]
__device__ float  g_c2[M_NODES * DD];           // nodes @ We1[128:256]
__device__ float  g_c3[27 * 27 * DD];           // table @ We1[256:384] + be1

__device__ __forceinline__ float gelu_exact(float x) {
    return 0.5f * x * (1.0f + erff(x * 0.70710678118654752440f));
}
__device__ __forceinline__ double gelu_exact_d(double x) {
    return 0.5 * x * (1.0 + erf(x * 0.7071067811865475244));
}

// ---- packed f32x2 helpers (used by sim kernel; IEEE per-lane) ----
__device__ __forceinline__ u64 pack2(float x) {
    unsigned int u = __float_as_uint(x);
    u64 r;
    asm("mov.b64 %0, {%1, %1};" : "=l"(r) : "r"(u));
    return r;
}
__device__ __forceinline__ void fma2(u64& d, u64 a, u64 b) {
    asm("fma.rn.f32x2 %0, %1, %2, %0;" : "+l"(d) : "l"(a), "l"(b));
}
__device__ __forceinline__ float2 unpack2(u64 v) {
    unsigned int lo, hi;
    asm("mov.b64 {%0, %1}, %2;" : "=r"(lo), "=r"(hi) : "l"(v));
    return make_float2(__uint_as_float(lo), __uint_as_float(hi));
}

// ---------------------------------------------------------------------------
// Kernel 1a: pos-MLP hidden layer (split from pos_table for launch-order
// control; bit-identical result).
// ---------------------------------------------------------------------------
__global__ void pos_a_kernel(const float* __restrict__ Wp1, const float* __restrict__ bp1) {
    int idx = blockIdx.x;
    float dy = (float)(idx / 27 - 13) * (1.0f / 13.0f);
    float dx = (float)(idx % 27 - 13) * (1.0f / 13.0f);
    int t = threadIdx.x;
    float v = dy * Wp1[t] + dx * Wp1[64 + t] + bp1[t];
    g_posh[idx * 64 + t] = gelu_exact(v);
}

// ---------------------------------------------------------------------------
// Kernel 1b: pos-MLP table from hidden layer (same accumulation order).
// ---------------------------------------------------------------------------
__global__ void pos_b_kernel(const float* __restrict__ Wp2, const float* __restrict__ bp2) {
    __shared__ float h[64];
    int idx = blockIdx.x;
    int t = threadIdx.x;
    if (t < 64) h[t] = g_posh[idx * 64 + t];
    __syncthreads();
    float acc = bp2[t];
    #pragma unroll 8
    for (int i = 0; i < 64; i++) acc += h[i] * Wp2[i * DD + t];
    g_table[idx * DD + t] = acc;
}

// ---------------------------------------------------------------------------
// Kernel 2: nodes = GELU(LN(tokens @ W_node + b_node)), fused L2-normalize.
// 32-row tile, 256 threads, 4x4 micro. Chunked-double accumulation (48 k per
// DADD); LN+GELU in double. (1519.7-best version, unchanged; now in ncu slot 4.)
// ---------------------------------------------------------------------------
__global__ void node_kernel(const float* __restrict__ feat, const float* __restrict__ Wn,
                            const float* __restrict__ bnode, const float* __restrict__ ln_g,
                            const float* __restrict__ ln_b, float* __restrict__ nodes_out) {
    __shared__ float As[16][36];
    __shared__ float4 Bs[16 * 32];
    __shared__ float Cs[32][132];
    __shared__ int s_base[32];
    int tid = threadIdx.x;
    int m0 = blockIdx.x * 32;
    if (tid < 32) {
        int m = m0 + tid;
        int b = m / NN, n = m % NN;
        s_base[tid] = b * (CC * NN) + n;
    }
    int tx = tid & 31, ty = tid >> 5;
    double dacc[4][4];
    #pragma unroll
    for (int i = 0; i < 4; i++)
        #pragma unroll
        for (int q = 0; q < 4; q++) dacc[i][q] = 0.0;
    float acc[4][4] = {};
    int cnt = 0;
    __syncthreads();
    for (int k0 = 0; k0 < CC; k0 += 16) {
        #pragma unroll
        for (int i = 0; i < 2; i++) {
            int e = tid + i * 256;
            int r = e & 31, cc = e >> 5;
            As[cc][r] = feat[s_base[r] + (k0 + cc) * NN];
        }
        const float4* Wg = (const float4*)(Wn + k0 * DD);
        Bs[tid] = Wg[tid];
        Bs[tid + 256] = Wg[tid + 256];
        __syncthreads();
        #pragma unroll
        for (int cc = 0; cc < 16; cc++) {
            float4 bv = Bs[cc * 32 + tx];
            float4 a = *(float4*)&As[cc][ty * 4];
            float av[4] = {a.x, a.y, a.z, a.w};
            #pragma unroll
            for (int i = 0; i < 4; i++) {
                acc[i][0] += av[i] * bv.x; acc[i][1] += av[i] * bv.y;
                acc[i][2] += av[i] * bv.z; acc[i][3] += av[i] * bv.w;
            }
        }
        if (++cnt == 3) {
            cnt = 0;
            #pragma unroll
            for (int i = 0; i < 4; i++)
                #pragma unroll
                for (int q = 0; q < 4; q++) {
                    dacc[i][q] += (double)acc[i][q];
                    acc[i][q] = 0.f;
                }
        }
        __syncthreads();
    }
    float4 bb = ((const float4*)bnode)[tx];
    #pragma unroll
    for (int i = 0; i < 4; i++) {
        int r = ty * 4 + i;
        *(float4*)&Cs[r][tx * 4] = make_float4(
            (float)(dacc[i][0] + (double)bb.x), (float)(dacc[i][1] + (double)bb.y),
            (float)(dacc[i][2] + (double)bb.z), (float)(dacc[i][3] + (double)bb.w));
    }
    __syncthreads();
    // LayerNorm + GELU in double + fused L2-normalize, one warp per row
    int lane = tx, w = ty;
    for (int rr = 0; rr < 4; rr++) {
        int r = w + 8 * rr;
        double x[4];
        double s = 0.0;
        #pragma unroll
        for (int q = 0; q < 4; q++) { x[q] = (double)Cs[r][lane + 32 * q]; s += x[q]; }
        #pragma unroll
        for (int o = 16; o > 0; o >>= 1) s += __shfl_xor_sync(~0u, s, o);
        double mu = s * (1.0 / 128.0);
        double vs = 0.0;
        #pragma unroll
        for (int q = 0; q < 4; q++) { double d = x[q] - mu; vs += d * d; }
        #pragma unroll
        for (int o = 16; o > 0; o >>= 1) vs += __shfl_xor_sync(~0u, vs, o);
        double rs = 1.0 / sqrt(vs * (1.0 / 128.0) + 1e-5);
        int row = m0 + r;
        float yf[4];
        double ssd = 0.0;
        #pragma unroll
        for (int q = 0; q < 4; q++) {
            int d = lane + 32 * q;
            double y = (x[q] - mu) * rs * (double)ln_g[d] + (double)ln_b[d];
            yf[q] = (float)gelu_exact_d(y);
            nodes_out[(size_t)row * DD + d] = yf[q];
            ssd += (double)yf[q] * yf[q];
        }
        #pragma unroll
        for (int o = 16; o > 0; o >>= 1) ssd += __shfl_xor_sync(~0u, ssd, o);
        double dinv = 1.0 / fmax(sqrt(ssd), 1e-12);
        if (lane == 0) g_dinv[row] = dinv;
        float inv = (float)dinv;
        #pragma unroll
        for (int q = 0; q < 4; q++)
            g_nrm[(size_t)row * DD + lane + 32 * q] = yf[q] * inv;
    }
}

// ---------------------------------------------------------------------------
// Kernel 4: sim = nrm @ nrm^T per batch. 32x32 tile, 64 threads, 4x4 micro,
// f32x2 packed FMA.
// ---------------------------------------------------------------------------
__global__ void sim_kernel() {
    __shared__ float As[32][36];
    __shared__ float Bs[32][36];
    int tid = threadIdx.x;
    const float* base = g_nrm + (size_t)blockIdx.z * (NN * DD);
    int by = blockIdx.y, bx = blockIdx.x;
    int tx = tid & 7, ty = tid >> 3;
    u64 acc2[2][4] = {};
    for (int k0 = 0; k0 < 128; k0 += 32) {
        #pragma unroll
        for (int it = 0; it < 4; it++) {
            int idx = tid + it * 64;
            int r = idx >> 3, kg = (idx & 7) * 4;
            int na = by * 32 + r;
            float4 v = (na < NN) ? *(const float4*)(base + (size_t)na * DD + k0 + kg)
                                 : make_float4(0.f, 0.f, 0.f, 0.f);
            As[kg + 0][r] = v.x; As[kg + 1][r] = v.y; As[kg + 2][r] = v.z; As[kg + 3][r] = v.w;
            int ma = bx * 32 + r;
            float4 u = (ma < NN) ? *(const float4*)(base + (size_t)ma * DD + k0 + kg)
                                 : make_float4(0.f, 0.f, 0.f, 0.f);
            Bs[kg + 0][r] = u.x; Bs[kg + 1][r] = u.y; Bs[kg + 2][r] = u.z; Bs[kg + 3][r] = u.w;
        }
        __syncthreads();
        #pragma unroll
        for (int k = 0; k < 32; k++) {
            ulonglong2 av = *(const ulonglong2*)&As[k][ty * 4];
            u64 ap[2] = {av.x, av.y};
            float4 b = *(float4*)&Bs[k][tx * 4];
            u64 b2[4] = {pack2(b.x), pack2(b.y), pack2(b.z), pack2(b.w)};
            #pragma unroll
            for (int p = 0; p < 2; p++)
                #pragma unroll
                for (int j = 0; j < 4; j++) fma2(acc2[p][j], ap[p], b2[j]);
        }
        __syncthreads();
    }
    float accf[4][4];
    #pragma unroll
    for (int p = 0; p < 2; p++)
        #pragma unroll
        for (int j = 0; j < 4; j++) {
            float2 v = unpack2(acc2[p][j]);
            accf[2 * p][j] = v.x;
            accf[2 * p + 1][j] = v.y;
        }
    float* simb = g_sim + (size_t)blockIdx.z * (NN * NN);
    #pragma unroll
    for (int i = 0; i < 4; i++) {
        int n0 = by * 32 + ty * 4 + i;
        if (n0 >= NN) break;
        int mcol = bx * 32 + tx * 4;
        if (mcol + 3 < NN) {
            *(float4*)(simb + n0 * NN + mcol) =
                make_float4(accf[i][0], accf[i][1], accf[i][2], accf[i][3]);
        } else {
            #pragma unroll
            for (int j = 0; j < 4; j++)
                if (mcol + j < NN) simb[n0 * NN + mcol + j] = accf[i][j];
        }
    }
}

// ---------------------------------------------------------------------------
// Kernel 5a: top-16 candidates, one WARP per row (register sort + warp argmax).
// ---------------------------------------------------------------------------
__global__ void cand_kernel() {
    int w = (blockIdx.x * blockDim.x + threadIdx.x) >> 5;
    int lane = threadIdx.x & 31;
    if (w >= M_NODES) return;
    int b = w / NN, n = w % NN;
    const float* row = g_sim + (size_t)b * (NN * NN) + n * NN;

    float v0, v1, v2, v3, v4, v5, v6;
    int   i0, i1, i2, i3, i4, i5, i6;
    {
        int m;
        m = lane;        i0 = m; v0 = (m != n) ? row[m] : -1e38f;
        m = lane + 32;   i1 = m; v1 = (m != n) ? row[m] : -1e38f;
        m = lane + 64;   i2 = m; v2 = (m != n) ? row[m] : -1e38f;
        m = lane + 96;   i3 = m; v3 = (m != n) ? row[m] : -1e38f;
        m = lane + 128;  i4 = m; v4 = (m != n) ? row[m] : -1e38f;
        m = lane + 160;  i5 = m; v5 = (m != n) ? row[m] : -1e38f;
        m = lane + 192;  i6 = m; v6 = (m < NN && m != n) ? row[m] : -1e38f;
    }
    #define CSWP(va, ia, vb, ib)                                             \
        { bool sw = (va < vb) || (va == vb && ia > ib);                      \
          float tv = sw ? vb : va; vb = sw ? va : vb; va = tv;               \
          int ti = sw ? ib : ia;   ib = sw ? ia : ib; ia = ti; }
    #pragma unroll
    for (int rnd = 0; rnd < 4; rnd++) {
        CSWP(v0, i0, v1, i1); CSWP(v2, i2, v3, i3); CSWP(v4, i4, v5, i5);
        if (rnd < 3) { CSWP(v1, i1, v2, i2); CSWP(v3, i3, v4, i4); CSWP(v5, i5, v6, i6); }
    }
    #undef CSWP

    int res = 0;
    #pragma unroll
    for (int k = 0; k < NC; k++) {
        float bv = v0; int bi = i0, bl = lane;
        #pragma unroll
        for (int o = 16; o > 0; o >>= 1) {
            float ov = __shfl_xor_sync(~0u, bv, o);
            int   oi = __shfl_xor_sync(~0u, bi, o);
            int   ol = __shfl_xor_sync(~0u, bl, o);
            bool take = (ov > bv) || (ov == bv && oi < bi);
            bv = take ? ov : bv; bi = take ? oi : bi; bl = take ? ol : bl;
        }
        if (lane == bl) {
            v0 = v1; i0 = i1; v1 = v2; i1 = i2; v2 = v3; i2 = i3;
            v3 = v4; i3 = i4; v4 = v5; i4 = i5; v5 = v6; i5 = i6;
            v6 = -1e38f;
        }
        if (lane == k) res = bi;
    }
    if (lane < NC) g_cand[w * NC + lane] = res;
}

// ---------------------------------------------------------------------------
// Kernel 5b: exact re-rank in double; fp32 round; stable sort; emit top-8.
// ---------------------------------------------------------------------------
__global__ void refine_kernel(const float* __restrict__ nodes, float* __restrict__ adj_out) {
    __shared__ float skey[8][NC];
    __shared__ int   sidx[8][NC];
    int wip = threadIdx.x >> 5;
    int lane = threadIdx.x & 31;
    int t = blockIdx.x * 8 + wip;
    if (t >= M_NODES) return;
    int b = t / NN;
    int rowbase = b * NN;
    double dinv_n = g_dinv[t];
    float4 av = ((const float4*)(nodes + (size_t)t * DD))[lane];
    int myc = (lane < NC) ? g_cand[t * NC + lane] : 0;
    #pragma unroll
    for (int c = 0; c < NC; c++) {
        int j = __shfl_sync(~0u, myc, c);
        float4 bv = ((const float4*)(nodes + (size_t)(rowbase + j) * DD))[lane];
        double p = (double)av.x * bv.x + (double)av.y * bv.y
                 + (double)av.z * bv.z + (double)av.w * bv.w;
        #pragma unroll
        for (int o = 16; o > 0; o >>= 1) p += __shfl_xor_sync(~0u, p, o);
        if (lane == c) {
            double sim = p * dinv_n * g_dinv[rowbase + j];
            skey[wip][c] = (float)sim;
            sidx[wip][c] = j;
        }
    }
    __syncwarp();
    if (lane == 0) {
        float kv[NC]; int ki[NC];
        #pragma unroll
        for (int i = 0; i < NC; i++) { kv[i] = skey[wip][i]; ki[i] = sidx[wip][i]; }
        #pragma unroll
        for (int i = 1; i < NC; i++) {
            float v = kv[i]; int id = ki[i];
            int p = i - 1;
            while (p >= 0 && (kv[p] < v || (kv[p] == v && ki[p] > id))) {
                kv[p + 1] = kv[p]; ki[p + 1] = ki[p]; p--;
            }
            kv[p + 1] = v; ki[p + 1] = id;
        }
        #pragma unroll
        for (int k = 0; k < TK; k++) {
            g_adj[t * TK + k] = ki[k];
            adj_out[t * TK + k] = (float)ki[k];
        }
    }
}

// ---------------------------------------------------------------------------
// Kernel 6: C{1,2} = nodes @ We1[seg*128 : seg*128+128].
// 64x128 tile, 256 threads, 8x4 micro, scalar FFMA.
// ---------------------------------------------------------------------------
__global__ void cgemm64_kernel(const float* __restrict__ nodes, const float* __restrict__ We1) {
    __shared__ float As[32][68];
    __shared__ float4 Bs[1024];
    int tid = threadIdx.x;
    int m0 = blockIdx.x * 64;
    int seg = blockIdx.y;
    float* C = seg ? g_c2 : g_c1;
    const float* W = We1 + (size_t)seg * 128 * DD;
    int tx = tid & 31, ty = tid >> 5;
    float acc[8][4] = {};
    for (int k0 = 0; k0 < 128; k0 += 32) {
        {
            int r = tid >> 2, cb = (tid & 3) * 8;
            const float4* p = (const float4*)(nodes + (size_t)(m0 + r) * DD + k0 + cb);
            float4 v0 = p[0], v1 = p[1];
            As[cb + 0][r] = v0.x; As[cb + 1][r] = v0.y; As[cb + 2][r] = v0.z; As[cb + 3][r] = v0.w;
            As[cb + 4][r] = v1.x; As[cb + 5][r] = v1.y; As[cb + 6][r] = v1.z; As[cb + 7][r] = v1.w;
        }
        {
            const float4* Wg = (const float4*)(W + k0 * DD);
            #pragma unroll
            for (int i = 0; i < 4; i++) Bs[tid + i * 256] = Wg[tid + i * 256];
        }
        __syncthreads();
        #pragma unroll
        for (int cc = 0; cc < 32; cc++) {
            float4 bv = Bs[cc * 32 + tx];
            float4 a0 = *(float4*)&As[cc][ty * 8];
            float4 a1 = *(float4*)&As[cc][ty * 8 + 4];
            float ar[8] = {a0.x, a0.y, a0.z, a0.w, a1.x, a1.y, a1.z, a1.w};
            #pragma unroll
            for (int i = 0; i < 8; i++) {
                acc[i][0] += ar[i] * bv.x; acc[i][1] += ar[i] * bv.y;
                acc[i][2] += ar[i] * bv.z; acc[i][3] += ar[i] * bv.w;
            }
        }
        __syncthreads();
    }
    #pragma unroll
    for (int i = 0; i < 8; i++) {
        int row = m0 + ty * 8 + i;
        ((float4*)(C + (size_t)row * DD))[tx] =
            make_float4(acc[i][0], acc[i][1], acc[i][2], acc[i][3]);
    }
}

// ---------------------------------------------------------------------------
// Kernel 7: C3 = table @ We1[256:384] + be1 (729 rows, tiny).
// ---------------------------------------------------------------------------
__global__ void c3_kernel(const float* __restrict__ We1, const float* __restrict__ be1) {
    __shared__ float ts[128];
    int row = blockIdx.x, t = threadIdx.x;
    ts[t] = g_table[row * DD + t];
    __syncthreads();
    float acc = be1[t];
    const float* W = We1 + (size_t)256 * DD;
    #pragma unroll 8
    for (int k = 0; k < 128; k++) acc += ts[k] * W[k * DD + t];
    g_c3[row * DD + t] = acc;
}

// ---------------------------------------------------------------------------
// Kernel 8: edges = GELU(C1[n] + C2[adj] + C3[disp]) @ We2 + be2.
// Double-buffered 64x128 tile, 8x4 micro (1519.7-best version).
// ---------------------------------------------------------------------------
__global__ void edge_fused64_kernel(const float* __restrict__ We2, const float* __restrict__ be2,
                                    float* __restrict__ edges_out) {
    __shared__ float As[2][32][68];
    __shared__ float4 Bs[2][1024];
    __shared__ int s1[64], s2[64], s3[64];
    int tid = threadIdx.x;
    int m0 = blockIdx.x * 64;
    if (tid < 64) {
        int e = m0 + tid;
        int bn = e >> 3;
        int b = bn / NN, n = bn - b * NN;
        int j = g_adj[e];
        s1[tid] = bn * DD;
        s2[tid] = (b * NN + j) * DD;
        int rn = n / 14, cn = n % 14, rj = j / 14, cj = j % 14;
        s3[tid] = ((rj - rn + 13) * 27 + (cj - cn + 13)) * DD;
    }
    __syncthreads();
    int tx = tid & 31, ty = tid >> 5;
    int gr = tid >> 2, gc = (tid & 3) * 8;
    float acc[8][4] = {};

    {
        const float* p1 = g_c1 + s1[gr] + gc;
        const float* p2 = g_c2 + s2[gr] + gc;
        const float* p3 = g_c3 + s3[gr] + gc;
        #pragma unroll
        for (int q = 0; q < 2; q++) {
            float4 v1 = *(const float4*)(p1 + q * 4);
            float4 v2 = *(const float4*)(p2 + q * 4);
            float4 v3 = *(const float4*)(p3 + q * 4);
            As[0][gc + q * 4 + 0][gr] = gelu_exact(v1.x + v2.x + v3.x);
            As[0][gc + q * 4 + 1][gr] = gelu_exact(v1.y + v2.y + v3.y);
            As[0][gc + q * 4 + 2][gr] = gelu_exact(v1.z + v2.z + v3.z);
            As[0][gc + q * 4 + 3][gr] = gelu_exact(v1.w + v2.w + v3.w);
        }
        const float4* Wg = (const float4*)We2;
        #pragma unroll
        for (int i = 0; i < 4; i++) Bs[0][tid + i * 256] = Wg[tid + i * 256];
    }
    __syncthreads();

    #pragma unroll
    for (int c = 0; c < 4; c++) {
        int buf = c & 1;
        float4 pre[6], bpre[4];
        if (c < 3) {
            int kn = (c + 1) * 32;
            const float* p1 = g_c1 + s1[gr] + kn + gc;
            const float* p2 = g_c2 + s2[gr] + kn + gc;
            const float* p3 = g_c3 + s3[gr] + kn + gc;
            pre[0] = *(const float4*)(p1);     pre[1] = *(const float4*)(p1 + 4);
            pre[2] = *(const float4*)(p2);     pre[3] = *(const float4*)(p2 + 4);
            pre[4] = *(const float4*)(p3);     pre[5] = *(const float4*)(p3 + 4);
            const float4* Wg = (const float4*)(We2 + kn * DD);
            #pragma unroll
            for (int i = 0; i < 4; i++) bpre[i] = Wg[tid + i * 256];
        }
        #pragma unroll
        for (int cc = 0; cc < 32; cc++) {
            float4 bv = Bs[buf][cc * 32 + tx];
            float4 a0 = *(float4*)&As[buf][cc][ty * 8];
            float4 a1 = *(float4*)&As[buf][cc][ty * 8 + 4];
            float ar[8] = {a0.x, a0.y, a0.z, a0.w, a1.x, a1.y, a1.z, a1.w};
            #pragma unroll
            for (int i = 0; i < 8; i++) {
                acc[i][0] += ar[i] * bv.x; acc[i][1] += ar[i] * bv.y;
                acc[i][2] += ar[i] * bv.z; acc[i][3] += ar[i] * bv.w;
            }
        }
        if (c < 3) {
            int nb = buf ^ 1;
            #pragma unroll
            for (int q = 0; q < 2; q++) {
                float4 v1 = pre[q], v2 = pre[2 + q], v3 = pre[4 + q];
                As[nb][gc + q * 4 + 0][gr] = gelu_exact(v1.x + v2.x + v3.x);
                As[nb][gc + q * 4 + 1][gr] = gelu_exact(v1.y + v2.y + v3.y);
                As[nb][gc + q * 4 + 2][gr] = gelu_exact(v1.z + v2.z + v3.z);
                As[nb][gc + q * 4 + 3][gr] = gelu_exact(v1.w + v2.w + v3.w);
            }
            #pragma unroll
            for (int i = 0; i < 4; i++) Bs[nb][tid + i * 256] = bpre[i];
        }
        __syncthreads();
    }

    float4 bb = ((const float4*)be2)[tx];
    #pragma unroll
    for (int i = 0; i < 8; i++) {
        int row = m0 + ty * 8 + i;
        ((float4*)(edges_out + (size_t)row * DD))[tx] =
            make_float4(acc[i][0] + bb.x, acc[i][1] + bb.y,
                        acc[i][2] + bb.z, acc[i][3] + bb.w);
    }
}

// ---------------------------------------------------------------------------
extern "C" void kernel_launch(void* const* d_in, const int* in_sizes, int n_in,
                              void* d_out, int out_size) {
    const float* feat = (const float*)d_in[0];
    const float* Wn   = (const float*)d_in[1];
    const float* bn   = (const float*)d_in[2];
    const float* lng  = (const float*)d_in[3];
    const float* lnb  = (const float*)d_in[4];
    const float* Wp1  = (const float*)d_in[5];
    const float* bp1  = (const float*)d_in[6];
    const float* Wp2  = (const float*)d_in[7];
    const float* bp2  = (const float*)d_in[8];
    const float* We1  = (const float*)d_in[9];
    const float* be1  = (const float*)d_in[10];
    const float* We2  = (const float*)d_in[11];
    const float* be2  = (const float*)d_in[12];

    float* out = (float*)d_out;
    float* nodes_out = out;                                   // B*N*D
    float* edges_out = out + (size_t)M_NODES * DD;            // B*N*K*D
    float* adj_out   = edges_out + (size_t)NE * DD;           // B*N*K

    // Launch order puts node_kernel in ncu's captured slot (#4).
    pos_a_kernel<<<729, 64>>>(Wp1, bp1);
    pos_b_kernel<<<729, 128>>>(Wp2, bp2);
    c3_kernel<<<729, 128>>>(We1, be1);
    node_kernel<<<M_NODES / 32, 256>>>(feat, Wn, bn, lng, lnb, nodes_out);
    sim_kernel<<<dim3(7, 7, BB), 64>>>();
    cand_kernel<<<(M_NODES * 32 + 255) / 256, 256>>>();
    refine_kernel<<<(M_NODES + 7) / 8, 256>>>(nodes_out, adj_out);
    cgemm64_kernel<<<dim3(M_NODES / 64, 2), 256>>>(nodes_out, We1);
    edge_fused64_kernel<<<NE / 64, 256>>>(We2, be2, edges_out);
}

// round 15
// speedup vs baseline: 1.0448x; 1.0152x over previous
#include <cuda_runtime.h>
#include <math.h>

// Problem constants
#define BB 128
#define CC 768
#define NN 196
#define DD 128
#define TK 8
#define NC 16                      // candidate count for exact re-rank
#define M_NODES (BB * NN)          // 25088
#define NE      (M_NODES * TK)     // 200704

typedef unsigned long long u64;

// Scratch (device globals; no allocations allowed)
__device__ float  g_pre[M_NODES * DD];          // node GEMM output (+bias), pre-LN
__device__ float  g_nrm[M_NODES * DD];          // normalized nodes (fp32, candidate stage)
__device__ float  g_sim[BB * NN * NN];          // similarity (fp32, candidate stage)
__device__ double g_dinv[M_NODES];              // double 1/||node||
__device__ int    g_cand[M_NODES * NC];         // top-16 fp32 candidates
__device__ int    g_adj[NE];                    // final top-8 indices
__device__ float  g_posh[729 * 64];             // pos-MLP hidden layer
__device__ float  g_table[27 * 27 * DD];        // pos-MLP table
__device__ float  g_c1[M_NODES * DD];           // nodes @ We1[0:128]
__device__ float  g_c2[M_NODES * DD];           // nodes @ We1[128:256]
__device__ float  g_c3[27 * 27 * DD];           // table @ We1[256:384] + be1

__device__ __forceinline__ float gelu_exact(float x) {
    return 0.5f * x * (1.0f + erff(x * 0.70710678118654752440f));
}
__device__ __forceinline__ double gelu_exact_d(double x) {
    return 0.5 * x * (1.0 + erf(x * 0.7071067811865475244));
}

// ---- packed f32x2 helpers (used by sim kernel; IEEE per-lane) ----
__device__ __forceinline__ u64 pack2(float x) {
    unsigned int u = __float_as_uint(x);
    u64 r;
    asm("mov.b64 %0, {%1, %1};" : "=l"(r) : "r"(u));
    return r;
}
__device__ __forceinline__ void fma2(u64& d, u64 a, u64 b) {
    asm("fma.rn.f32x2 %0, %1, %2, %0;" : "+l"(d) : "l"(a), "l"(b));
}
__device__ __forceinline__ float2 unpack2(u64 v) {
    unsigned int lo, hi;
    asm("mov.b64 {%0, %1}, %2;" : "=r"(lo), "=r"(hi) : "l"(v));
    return make_float2(__uint_as_float(lo), __uint_as_float(hi));
}

// ---------------------------------------------------------------------------
// Kernel 1a: pos-MLP hidden layer.
// ---------------------------------------------------------------------------
__global__ void pos_a_kernel(const float* __restrict__ Wp1, const float* __restrict__ bp1) {
    int idx = blockIdx.x;
    float dy = (float)(idx / 27 - 13) * (1.0f / 13.0f);
    float dx = (float)(idx % 27 - 13) * (1.0f / 13.0f);
    int t = threadIdx.x;
    float v = dy * Wp1[t] + dx * Wp1[64 + t] + bp1[t];
    g_posh[idx * 64 + t] = gelu_exact(v);
}

// ---------------------------------------------------------------------------
// Kernel 1b: pos-MLP table from hidden layer (same accumulation order).
// ---------------------------------------------------------------------------
__global__ void pos_b_kernel(const float* __restrict__ Wp2, const float* __restrict__ bp2) {
    __shared__ float h[64];
    int idx = blockIdx.x;
    int t = threadIdx.x;
    if (t < 64) h[t] = g_posh[idx * 64 + t];
    __syncthreads();
    float acc = bp2[t];
    #pragma unroll 8
    for (int i = 0; i < 64; i++) acc += h[i] * Wp2[i * DD + t];
    g_table[idx * DD + t] = acc;
}

// ---------------------------------------------------------------------------
// Kernel 2a: node GEMM: g_pre = tokens @ W_node + b_node (fp32-rounded).
// 32-row tile, 256 threads, 4x4 micro, chunked-double accumulation (48 k per
// DADD flush, identical boundaries/k-order as before => bit-identical values).
// Register prefetch: chunk c+1's LDGs issue before chunk c's FMA block.
// ---------------------------------------------------------------------------
__global__ void node_gemm_kernel(const float* __restrict__ feat, const float* __restrict__ Wn,
                                 const float* __restrict__ bnode) {
    __shared__ float As[16][36];
    __shared__ float4 Bs[16 * 32];
    __shared__ int s_base[32];
    int tid = threadIdx.x;
    int m0 = blockIdx.x * 32;
    if (tid < 32) {
        int m = m0 + tid;
        int b = m / NN, n = m % NN;
        s_base[tid] = b * (CC * NN) + n;
    }
    int tx = tid & 31, ty = tid >> 5;
    int e0r = tid & 31, e0c = tid >> 5;                 // element 0 mapping
    int e1 = tid + 256;
    int e1r = e1 & 31, e1c = e1 >> 5;                   // element 1 mapping
    double dacc[4][4];
    #pragma unroll
    for (int i = 0; i < 4; i++)
        #pragma unroll
        for (int q = 0; q < 4; q++) dacc[i][q] = 0.0;
    float acc[4][4] = {};
    int cnt = 0;
    __syncthreads();

    // prefetch chunk 0
    float pf0 = feat[s_base[e0r] + e0c * NN];
    float pf1 = feat[s_base[e1r] + e1c * NN];
    float4 pfB0 = ((const float4*)Wn)[tid];
    float4 pfB1 = ((const float4*)Wn)[tid + 256];

    for (int k0 = 0; k0 < CC; k0 += 16) {
        As[e0c][e0r] = pf0;
        As[e1c][e1r] = pf1;
        Bs[tid] = pfB0;
        Bs[tid + 256] = pfB1;
        __syncthreads();
        if (k0 + 16 < CC) {
            pf0 = feat[s_base[e0r] + (k0 + 16 + e0c) * NN];
            pf1 = feat[s_base[e1r] + (k0 + 16 + e1c) * NN];
            const float4* Wg = (const float4*)(Wn + (k0 + 16) * DD);
            pfB0 = Wg[tid];
            pfB1 = Wg[tid + 256];
        }
        #pragma unroll
        for (int cc = 0; cc < 16; cc++) {
            float4 bv = Bs[cc * 32 + tx];
            float4 a = *(float4*)&As[cc][ty * 4];
            float av[4] = {a.x, a.y, a.z, a.w};
            #pragma unroll
            for (int i = 0; i < 4; i++) {
                acc[i][0] += av[i] * bv.x; acc[i][1] += av[i] * bv.y;
                acc[i][2] += av[i] * bv.z; acc[i][3] += av[i] * bv.w;
            }
        }
        if (++cnt == 3) {
            cnt = 0;
            #pragma unroll
            for (int i = 0; i < 4; i++)
                #pragma unroll
                for (int q = 0; q < 4; q++) {
                    dacc[i][q] += (double)acc[i][q];
                    acc[i][q] = 0.f;
                }
        }
        __syncthreads();
    }
    float4 bb = ((const float4*)bnode)[tx];
    #pragma unroll
    for (int i = 0; i < 4; i++) {
        int row = m0 + ty * 4 + i;
        *(float4*)(g_pre + (size_t)row * DD + tx * 4) = make_float4(
            (float)(dacc[i][0] + (double)bb.x), (float)(dacc[i][1] + (double)bb.y),
            (float)(dacc[i][2] + (double)bb.z), (float)(dacc[i][3] + (double)bb.w));
    }
}

// ---------------------------------------------------------------------------
// Kernel 2b: node tail: LN + GELU (double, verbatim) + fused L2-normalize.
// Warp per row, 8 rows per block, high occupancy. Reads g_pre (same fp32
// values the fused kernel had in Cs) => bit-identical outputs.
// ---------------------------------------------------------------------------
__global__ void node_tail_kernel(const float* __restrict__ ln_g, const float* __restrict__ ln_b,
                                 float* __restrict__ nodes_out) {
    int wip = threadIdx.x >> 5;
    int lane = threadIdx.x & 31;
    int row = blockIdx.x * 8 + wip;
    if (row >= M_NODES) return;
    double x[4];
    double s = 0.0;
    #pragma unroll
    for (int q = 0; q < 4; q++) {
        x[q] = (double)g_pre[(size_t)row * DD + lane + 32 * q];
        s += x[q];
    }
    #pragma unroll
    for (int o = 16; o > 0; o >>= 1) s += __shfl_xor_sync(~0u, s, o);
    double mu = s * (1.0 / 128.0);
    double vs = 0.0;
    #pragma unroll
    for (int q = 0; q < 4; q++) { double d = x[q] - mu; vs += d * d; }
    #pragma unroll
    for (int o = 16; o > 0; o >>= 1) vs += __shfl_xor_sync(~0u, vs, o);
    double rs = 1.0 / sqrt(vs * (1.0 / 128.0) + 1e-5);
    float yf[4];
    double ssd = 0.0;
    #pragma unroll
    for (int q = 0; q < 4; q++) {
        int d = lane + 32 * q;
        double y = (x[q] - mu) * rs * (double)ln_g[d] + (double)ln_b[d];
        yf[q] = (float)gelu_exact_d(y);
        nodes_out[(size_t)row * DD + d] = yf[q];
        ssd += (double)yf[q] * yf[q];
    }
    #pragma unroll
    for (int o = 16; o > 0; o >>= 1) ssd += __shfl_xor_sync(~0u, ssd, o);
    double dinv = 1.0 / fmax(sqrt(ssd), 1e-12);
    if (lane == 0) g_dinv[row] = dinv;
    float inv = (float)dinv;
    #pragma unroll
    for (int q = 0; q < 4; q++)
        g_nrm[(size_t)row * DD + lane + 32 * q] = yf[q] * inv;
}

// ---------------------------------------------------------------------------
// Kernel 4: sim = nrm @ nrm^T per batch. 32x32 tile, 64 threads, 4x4 micro,
// f32x2 packed FMA.
// ---------------------------------------------------------------------------
__global__ void sim_kernel() {
    __shared__ float As[32][36];
    __shared__ float Bs[32][36];
    int tid = threadIdx.x;
    const float* base = g_nrm + (size_t)blockIdx.z * (NN * DD);
    int by = blockIdx.y, bx = blockIdx.x;
    int tx = tid & 7, ty = tid >> 3;
    u64 acc2[2][4] = {};
    for (int k0 = 0; k0 < 128; k0 += 32) {
        #pragma unroll
        for (int it = 0; it < 4; it++) {
            int idx = tid + it * 64;
            int r = idx >> 3, kg = (idx & 7) * 4;
            int na = by * 32 + r;
            float4 v = (na < NN) ? *(const float4*)(base + (size_t)na * DD + k0 + kg)
                                 : make_float4(0.f, 0.f, 0.f, 0.f);
            As[kg + 0][r] = v.x; As[kg + 1][r] = v.y; As[kg + 2][r] = v.z; As[kg + 3][r] = v.w;
            int ma = bx * 32 + r;
            float4 u = (ma < NN) ? *(const float4*)(base + (size_t)ma * DD + k0 + kg)
                                 : make_float4(0.f, 0.f, 0.f, 0.f);
            Bs[kg + 0][r] = u.x; Bs[kg + 1][r] = u.y; Bs[kg + 2][r] = u.z; Bs[kg + 3][r] = u.w;
        }
        __syncthreads();
        #pragma unroll
        for (int k = 0; k < 32; k++) {
            ulonglong2 av = *(const ulonglong2*)&As[k][ty * 4];
            u64 ap[2] = {av.x, av.y};
            float4 b = *(float4*)&Bs[k][tx * 4];
            u64 b2[4] = {pack2(b.x), pack2(b.y), pack2(b.z), pack2(b.w)};
            #pragma unroll
            for (int p = 0; p < 2; p++)
                #pragma unroll
                for (int j = 0; j < 4; j++) fma2(acc2[p][j], ap[p], b2[j]);
        }
        __syncthreads();
    }
    float accf[4][4];
    #pragma unroll
    for (int p = 0; p < 2; p++)
        #pragma unroll
        for (int j = 0; j < 4; j++) {
            float2 v = unpack2(acc2[p][j]);
            accf[2 * p][j] = v.x;
            accf[2 * p + 1][j] = v.y;
        }
    float* simb = g_sim + (size_t)blockIdx.z * (NN * NN);
    #pragma unroll
    for (int i = 0; i < 4; i++) {
        int n0 = by * 32 + ty * 4 + i;
        if (n0 >= NN) break;
        int mcol = bx * 32 + tx * 4;
        if (mcol + 3 < NN) {
            *(float4*)(simb + n0 * NN + mcol) =
                make_float4(accf[i][0], accf[i][1], accf[i][2], accf[i][3]);
        } else {
            #pragma unroll
            for (int j = 0; j < 4; j++)
                if (mcol + j < NN) simb[n0 * NN + mcol + j] = accf[i][j];
        }
    }
}

// ---------------------------------------------------------------------------
// Kernel 5a: top-16 candidates, one WARP per row (register sort + warp argmax).
// ---------------------------------------------------------------------------
__global__ void cand_kernel() {
    int w = (blockIdx.x * blockDim.x + threadIdx.x) >> 5;
    int lane = threadIdx.x & 31;
    if (w >= M_NODES) return;
    int b = w / NN, n = w % NN;
    const float* row = g_sim + (size_t)b * (NN * NN) + n * NN;

    float v0, v1, v2, v3, v4, v5, v6;
    int   i0, i1, i2, i3, i4, i5, i6;
    {
        int m;
        m = lane;        i0 = m; v0 = (m != n) ? row[m] : -1e38f;
        m = lane + 32;   i1 = m; v1 = (m != n) ? row[m] : -1e38f;
        m = lane + 64;   i2 = m; v2 = (m != n) ? row[m] : -1e38f;
        m = lane + 96;   i3 = m; v3 = (m != n) ? row[m] : -1e38f;
        m = lane + 128;  i4 = m; v4 = (m != n) ? row[m] : -1e38f;
        m = lane + 160;  i5 = m; v5 = (m != n) ? row[m] : -1e38f;
        m = lane + 192;  i6 = m; v6 = (m < NN && m != n) ? row[m] : -1e38f;
    }
    #define CSWP(va, ia, vb, ib)                                             \
        { bool sw = (va < vb) || (va == vb && ia > ib);                      \
          float tv = sw ? vb : va; vb = sw ? va : vb; va = tv;               \
          int ti = sw ? ib : ia;   ib = sw ? ia : ib; ia = ti; }
    #pragma unroll
    for (int rnd = 0; rnd < 4; rnd++) {
        CSWP(v0, i0, v1, i1); CSWP(v2, i2, v3, i3); CSWP(v4, i4, v5, i5);
        if (rnd < 3) { CSWP(v1, i1, v2, i2); CSWP(v3, i3, v4, i4); CSWP(v5, i5, v6, i6); }
    }
    #undef CSWP

    int res = 0;
    #pragma unroll
    for (int k = 0; k < NC; k++) {
        float bv = v0; int bi = i0, bl = lane;
        #pragma unroll
        for (int o = 16; o > 0; o >>= 1) {
            float ov = __shfl_xor_sync(~0u, bv, o);
            int   oi = __shfl_xor_sync(~0u, bi, o);
            int   ol = __shfl_xor_sync(~0u, bl, o);
            bool take = (ov > bv) || (ov == bv && oi < bi);
            bv = take ? ov : bv; bi = take ? oi : bi; bl = take ? ol : bl;
        }
        if (lane == bl) {
            v0 = v1; i0 = i1; v1 = v2; i1 = i2; v2 = v3; i2 = i3;
            v3 = v4; i3 = i4; v4 = v5; i4 = i5; v5 = v6; i5 = i6;
            v6 = -1e38f;
        }
        if (lane == k) res = bi;
    }
    if (lane < NC) g_cand[w * NC + lane] = res;
}

// ---------------------------------------------------------------------------
// Kernel 5b: exact re-rank in double; fp32 round; stable sort; emit top-8.
// ---------------------------------------------------------------------------
__global__ void refine_kernel(const float* __restrict__ nodes, float* __restrict__ adj_out) {
    __shared__ float skey[8][NC];
    __shared__ int   sidx[8][NC];
    int wip = threadIdx.x >> 5;
    int lane = threadIdx.x & 31;
    int t = blockIdx.x * 8 + wip;
    if (t >= M_NODES) return;
    int b = t / NN;
    int rowbase = b * NN;
    double dinv_n = g_dinv[t];
    float4 av = ((const float4*)(nodes + (size_t)t * DD))[lane];
    int myc = (lane < NC) ? g_cand[t * NC + lane] : 0;
    #pragma unroll
    for (int c = 0; c < NC; c++) {
        int j = __shfl_sync(~0u, myc, c);
        float4 bv = ((const float4*)(nodes + (size_t)(rowbase + j) * DD))[lane];
        double p = (double)av.x * bv.x + (double)av.y * bv.y
                 + (double)av.z * bv.z + (double)av.w * bv.w;
        #pragma unroll
        for (int o = 16; o > 0; o >>= 1) p += __shfl_xor_sync(~0u, p, o);
        if (lane == c) {
            double sim = p * dinv_n * g_dinv[rowbase + j];
            skey[wip][c] = (float)sim;
            sidx[wip][c] = j;
        }
    }
    __syncwarp();
    if (lane == 0) {
        float kv[NC]; int ki[NC];
        #pragma unroll
        for (int i = 0; i < NC; i++) { kv[i] = skey[wip][i]; ki[i] = sidx[wip][i]; }
        #pragma unroll
        for (int i = 1; i < NC; i++) {
            float v = kv[i]; int id = ki[i];
            int p = i - 1;
            while (p >= 0 && (kv[p] < v || (kv[p] == v && ki[p] > id))) {
                kv[p + 1] = kv[p]; ki[p + 1] = ki[p]; p--;
            }
            kv[p + 1] = v; ki[p + 1] = id;
        }
        #pragma unroll
        for (int k = 0; k < TK; k++) {
            g_adj[t * TK + k] = ki[k];
            adj_out[t * TK + k] = (float)ki[k];
        }
    }
}

// ---------------------------------------------------------------------------
// Kernel 6: C{1,2} = nodes @ We1[seg*128 : seg*128+128].
// 64x128 tile, 256 threads, 8x4 micro, scalar FFMA.
// ---------------------------------------------------------------------------
__global__ void cgemm64_kernel(const float* __restrict__ nodes, const float* __restrict__ We1) {
    __shared__ float As[32][68];
    __shared__ float4 Bs[1024];
    int tid = threadIdx.x;
    int m0 = blockIdx.x * 64;
    int seg = blockIdx.y;
    float* C = seg ? g_c2 : g_c1;
    const float* W = We1 + (size_t)seg * 128 * DD;
    int tx = tid & 31, ty = tid >> 5;
    float acc[8][4] = {};
    for (int k0 = 0; k0 < 128; k0 += 32) {
        {
            int r = tid >> 2, cb = (tid & 3) * 8;
            const float4* p = (const float4*)(nodes + (size_t)(m0 + r) * DD + k0 + cb);
            float4 v0 = p[0], v1 = p[1];
            As[cb + 0][r] = v0.x; As[cb + 1][r] = v0.y; As[cb + 2][r] = v0.z; As[cb + 3][r] = v0.w;
            As[cb + 4][r] = v1.x; As[cb + 5][r] = v1.y; As[cb + 6][r] = v1.z; As[cb + 7][r] = v1.w;
        }
        {
            const float4* Wg = (const float4*)(W + k0 * DD);
            #pragma unroll
            for (int i = 0; i < 4; i++) Bs[tid + i * 256] = Wg[tid + i * 256];
        }
        __syncthreads();
        #pragma unroll
        for (int cc = 0; cc < 32; cc++) {
            float4 bv = Bs[cc * 32 + tx];
            float4 a0 = *(float4*)&As[cc][ty * 8];
            float4 a1 = *(float4*)&As[cc][ty * 8 + 4];
            float ar[8] = {a0.x, a0.y, a0.z, a0.w, a1.x, a1.y, a1.z, a1.w};
            #pragma unroll
            for (int i = 0; i < 8; i++) {
                acc[i][0] += ar[i] * bv.x; acc[i][1] += ar[i] * bv.y;
                acc[i][2] += ar[i] * bv.z; acc[i][3] += ar[i] * bv.w;
            }
        }
        __syncthreads();
    }
    #pragma unroll
    for (int i = 0; i < 8; i++) {
        int row = m0 + ty * 8 + i;
        ((float4*)(C + (size_t)row * DD))[tx] =
            make_float4(acc[i][0], acc[i][1], acc[i][2], acc[i][3]);
    }
}

// ---------------------------------------------------------------------------
// Kernel 7: C3 = table @ We1[256:384] + be1 (729 rows, tiny).
// ---------------------------------------------------------------------------
__global__ void c3_kernel(const float* __restrict__ We1, const float* __restrict__ be1) {
    __shared__ float ts[128];
    int row = blockIdx.x, t = threadIdx.x;
    ts[t] = g_table[row * DD + t];
    __syncthreads();
    float acc = be1[t];
    const float* W = We1 + (size_t)256 * DD;
    #pragma unroll 8
    for (int k = 0; k < 128; k++) acc += ts[k] * W[k * DD + t];
    g_c3[row * DD + t] = acc;
}

// ---------------------------------------------------------------------------
// Kernel 8: edges = GELU(C1[n] + C2[adj] + C3[disp]) @ We2 + be2.
// Double-buffered 64x128 tile, 8x4 micro (1519.7-best version).
// ---------------------------------------------------------------------------
__global__ void edge_fused64_kernel(const float* __restrict__ We2, const float* __restrict__ be2,
                                    float* __restrict__ edges_out) {
    __shared__ float As[2][32][68];
    __shared__ float4 Bs[2][1024];
    __shared__ int s1[64], s2[64], s3[64];
    int tid = threadIdx.x;
    int m0 = blockIdx.x * 64;
    if (tid < 64) {
        int e = m0 + tid;
        int bn = e >> 3;
        int b = bn / NN, n = bn - b * NN;
        int j = g_adj[e];
        s1[tid] = bn * DD;
        s2[tid] = (b * NN + j) * DD;
        int rn = n / 14, cn = n % 14, rj = j / 14, cj = j % 14;
        s3[tid] = ((rj - rn + 13) * 27 + (cj - cn + 13)) * DD;
    }
    __syncthreads();
    int tx = tid & 31, ty = tid >> 5;
    int gr = tid >> 2, gc = (tid & 3) * 8;
    float acc[8][4] = {};

    {
        const float* p1 = g_c1 + s1[gr] + gc;
        const float* p2 = g_c2 + s2[gr] + gc;
        const float* p3 = g_c3 + s3[gr] + gc;
        #pragma unroll
        for (int q = 0; q < 2; q++) {
            float4 v1 = *(const float4*)(p1 + q * 4);
            float4 v2 = *(const float4*)(p2 + q * 4);
            float4 v3 = *(const float4*)(p3 + q * 4);
            As[0][gc + q * 4 + 0][gr] = gelu_exact(v1.x + v2.x + v3.x);
            As[0][gc + q * 4 + 1][gr] = gelu_exact(v1.y + v2.y + v3.y);
            As[0][gc + q * 4 + 2][gr] = gelu_exact(v1.z + v2.z + v3.z);
            As[0][gc + q * 4 + 3][gr] = gelu_exact(v1.w + v2.w + v3.w);
        }
        const float4* Wg = (const float4*)We2;
        #pragma unroll
        for (int i = 0; i < 4; i++) Bs[0][tid + i * 256] = Wg[tid + i * 256];
    }
    __syncthreads();

    #pragma unroll
    for (int c = 0; c < 4; c++) {
        int buf = c & 1;
        float4 pre[6], bpre[4];
        if (c < 3) {
            int kn = (c + 1) * 32;
            const float* p1 = g_c1 + s1[gr] + kn + gc;
            const float* p2 = g_c2 + s2[gr] + kn + gc;
            const float* p3 = g_c3 + s3[gr] + kn + gc;
            pre[0] = *(const float4*)(p1);     pre[1] = *(const float4*)(p1 + 4);
            pre[2] = *(const float4*)(p2);     pre[3] = *(const float4*)(p2 + 4);
            pre[4] = *(const float4*)(p3);     pre[5] = *(const float4*)(p3 + 4);
            const float4* Wg = (const float4*)(We2 + kn * DD);
            #pragma unroll
            for (int i = 0; i < 4; i++) bpre[i] = Wg[tid + i * 256];
        }
        #pragma unroll
        for (int cc = 0; cc < 32; cc++) {
            float4 bv = Bs[buf][cc * 32 + tx];
            float4 a0 = *(float4*)&As[buf][cc][ty * 8];
            float4 a1 = *(float4*)&As[buf][cc][ty * 8 + 4];
            float ar[8] = {a0.x, a0.y, a0.z, a0.w, a1.x, a1.y, a1.z, a1.w};
            #pragma unroll
            for (int i = 0; i < 8; i++) {
                acc[i][0] += ar[i] * bv.x; acc[i][1] += ar[i] * bv.y;
                acc[i][2] += ar[i] * bv.z; acc[i][3] += ar[i] * bv.w;
            }
        }
        if (c < 3) {
            int nb = buf ^ 1;
            #pragma unroll
            for (int q = 0; q < 2; q++) {
                float4 v1 = pre[q], v2 = pre[2 + q], v3 = pre[4 + q];
                As[nb][gc + q * 4 + 0][gr] = gelu_exact(v1.x + v2.x + v3.x);
                As[nb][gc + q * 4 + 1][gr] = gelu_exact(v1.y + v2.y + v3.y);
                As[nb][gc + q * 4 + 2][gr] = gelu_exact(v1.z + v2.z + v3.z);
                As[nb][gc + q * 4 + 3][gr] = gelu_exact(v1.w + v2.w + v3.w);
            }
            #pragma unroll
            for (int i = 0; i < 4; i++) Bs[nb][tid + i * 256] = bpre[i];
        }
        __syncthreads();
    }

    float4 bb = ((const float4*)be2)[tx];
    #pragma unroll
    for (int i = 0; i < 8; i++) {
        int row = m0 + ty * 8 + i;
        ((float4*)(edges_out + (size_t)row * DD))[tx] =
            make_float4(acc[i][0] + bb.x, acc[i][1] + bb.y,
                        acc[i][2] + bb.z, acc[i][3] + bb.w);
    }
}

// ---------------------------------------------------------------------------
extern "C" void kernel_launch(void* const* d_in, const int* in_sizes, int n_in,
                              void* d_out, int out_size) {
    const float* feat = (const float*)d_in[0];
    const float* Wn   = (const float*)d_in[1];
    const float* bn   = (const float*)d_in[2];
    const float* lng  = (const float*)d_in[3];
    const float* lnb  = (const float*)d_in[4];
    const float* Wp1  = (const float*)d_in[5];
    const float* bp1  = (const float*)d_in[6];
    const float* Wp2  = (const float*)d_in[7];
    const float* bp2  = (const float*)d_in[8];
    const float* We1  = (const float*)d_in[9];
    const float* be1  = (const float*)d_in[10];
    const float* We2  = (const float*)d_in[11];
    const float* be2  = (const float*)d_in[12];

    float* out = (float*)d_out;
    float* nodes_out = out;                                   // B*N*D
    float* edges_out = out + (size_t)M_NODES * DD;            // B*N*K*D
    float* adj_out   = edges_out + (size_t)NE * DD;           // B*N*K

    // node_gemm occupies ncu's captured slot (#4) for next-round verification.
    pos_a_kernel<<<729, 64>>>(Wp1, bp1);
    pos_b_kernel<<<729, 128>>>(Wp2, bp2);
    c3_kernel<<<729, 128>>>(We1, be1);
    node_gemm_kernel<<<M_NODES / 32, 256>>>(feat, Wn, bn);
    node_tail_kernel<<<M_NODES / 8, 256>>>(lng, lnb, nodes_out);
    sim_kernel<<<dim3(7, 7, BB), 64>>>();
    cand_kernel<<<(M_NODES * 32 + 255) / 256, 256>>>();
    refine_kernel<<<(M_NODES + 7) / 8, 256>>>(nodes_out, adj_out);
    cgemm64_kernel<<<dim3(M_NODES / 64, 2), 256>>>(nodes_out, We1);
    edge_fused64_kernel<<<NE / 64, 256>>>(We2, be2, edges_out);
}

// round 16
// speedup vs baseline: 1.2668x; 1.2124x over previous
#include <cuda_runtime.h>
#include <math.h>

// Problem constants
#define BB 128
#define CC 768
#define NN 196
#define DD 128
#define TK 8
#define NC 16                      // candidate count for exact re-rank
#define M_NODES (BB * NN)          // 25088
#define NE      (M_NODES * TK)     // 200704

typedef unsigned long long u64;

// Scratch (device globals; no allocations allowed)
__device__ float  g_pre[M_NODES * DD];          // node GEMM output (+bias), pre-LN
__device__ float  g_nrm[M_NODES * DD];          // normalized nodes (fp32, candidate stage)
__device__ float  g_sim[BB * NN * NN];          // similarity (fp32, candidate stage)
__device__ double g_dinv[M_NODES];              // double 1/||node||
__device__ int    g_cand[M_NODES * NC];         // top-16 fp32 candidates
__device__ int    g_adj[NE];                    // final top-8 indices
__device__ float  g_posh[729 * 64];             // pos-MLP hidden layer
__device__ float  g_table[27 * 27 * DD];        // pos-MLP table
__device__ float  g_c1[M_NODES * DD];           // nodes @ We1[0:128]
__device__ float  g_c2[M_NODES * DD];           // nodes @ We1[128:256]
__device__ float  g_c3[27 * 27 * DD];           // table @ We1[256:384] + be1

__device__ __forceinline__ float gelu_exact(float x) {
    return 0.5f * x * (1.0f + erff(x * 0.70710678118654752440f));
}

// ---- packed f32x2 helpers (used by sim kernel; IEEE per-lane) ----
__device__ __forceinline__ u64 pack2(float x) {
    unsigned int u = __float_as_uint(x);
    u64 r;
    asm("mov.b64 %0, {%1, %1};" : "=l"(r) : "r"(u));
    return r;
}
__device__ __forceinline__ void fma2(u64& d, u64 a, u64 b) {
    asm("fma.rn.f32x2 %0, %1, %2, %0;" : "+l"(d) : "l"(a), "l"(b));
}
__device__ __forceinline__ float2 unpack2(u64 v) {
    unsigned int lo, hi;
    asm("mov.b64 {%0, %1}, %2;" : "=r"(lo), "=r"(hi) : "l"(v));
    return make_float2(__uint_as_float(lo), __uint_as_float(hi));
}

// ---------------------------------------------------------------------------
// Kernel 1a: pos-MLP hidden layer.
// ---------------------------------------------------------------------------
__global__ void pos_a_kernel(const float* __restrict__ Wp1, const float* __restrict__ bp1) {
    int idx = blockIdx.x;
    float dy = (float)(idx / 27 - 13) * (1.0f / 13.0f);
    float dx = (float)(idx % 27 - 13) * (1.0f / 13.0f);
    int t = threadIdx.x;
    float v = dy * Wp1[t] + dx * Wp1[64 + t] + bp1[t];
    g_posh[idx * 64 + t] = gelu_exact(v);
}

// ---------------------------------------------------------------------------
// Kernel 1b: pos-MLP table from hidden layer (same accumulation order).
// ---------------------------------------------------------------------------
__global__ void pos_b_kernel(const float* __restrict__ Wp2, const float* __restrict__ bp2) {
    __shared__ float h[64];
    int idx = blockIdx.x;
    int t = threadIdx.x;
    if (t < 64) h[t] = g_posh[idx * 64 + t];
    __syncthreads();
    float acc = bp2[t];
    #pragma unroll 8
    for (int i = 0; i < 64; i++) acc += h[i] * Wp2[i * DD + t];
    g_table[idx * DD + t] = acc;
}

// ---------------------------------------------------------------------------
// Kernel 2a: node GEMM: g_pre = tokens @ W_node + b_node (fp32-rounded).
// 32-row tile, 256 threads, 4x4 micro, chunked-double accumulation (48 k per
// DADD flush). Register prefetch pipeline. (r15 version, measured 342 us.)
// ---------------------------------------------------------------------------
__global__ void node_gemm_kernel(const float* __restrict__ feat, const float* __restrict__ Wn,
                                 const float* __restrict__ bnode) {
    __shared__ float As[16][36];
    __shared__ float4 Bs[16 * 32];
    __shared__ int s_base[32];
    int tid = threadIdx.x;
    int m0 = blockIdx.x * 32;
    if (tid < 32) {
        int m = m0 + tid;
        int b = m / NN, n = m % NN;
        s_base[tid] = b * (CC * NN) + n;
    }
    int tx = tid & 31, ty = tid >> 5;
    int e0r = tid & 31, e0c = tid >> 5;
    int e1 = tid + 256;
    int e1r = e1 & 31, e1c = e1 >> 5;
    double dacc[4][4];
    #pragma unroll
    for (int i = 0; i < 4; i++)
        #pragma unroll
        for (int q = 0; q < 4; q++) dacc[i][q] = 0.0;
    float acc[4][4] = {};
    int cnt = 0;
    __syncthreads();

    float pf0 = feat[s_base[e0r] + e0c * NN];
    float pf1 = feat[s_base[e1r] + e1c * NN];
    float4 pfB0 = ((const float4*)Wn)[tid];
    float4 pfB1 = ((const float4*)Wn)[tid + 256];

    for (int k0 = 0; k0 < CC; k0 += 16) {
        As[e0c][e0r] = pf0;
        As[e1c][e1r] = pf1;
        Bs[tid] = pfB0;
        Bs[tid + 256] = pfB1;
        __syncthreads();
        if (k0 + 16 < CC) {
            pf0 = feat[s_base[e0r] + (k0 + 16 + e0c) * NN];
            pf1 = feat[s_base[e1r] + (k0 + 16 + e1c) * NN];
            const float4* Wg = (const float4*)(Wn + (k0 + 16) * DD);
            pfB0 = Wg[tid];
            pfB1 = Wg[tid + 256];
        }
        #pragma unroll
        for (int cc = 0; cc < 16; cc++) {
            float4 bv = Bs[cc * 32 + tx];
            float4 a = *(float4*)&As[cc][ty * 4];
            float av[4] = {a.x, a.y, a.z, a.w};
            #pragma unroll
            for (int i = 0; i < 4; i++) {
                acc[i][0] += av[i] * bv.x; acc[i][1] += av[i] * bv.y;
                acc[i][2] += av[i] * bv.z; acc[i][3] += av[i] * bv.w;
            }
        }
        if (++cnt == 3) {
            cnt = 0;
            #pragma unroll
            for (int i = 0; i < 4; i++)
                #pragma unroll
                for (int q = 0; q < 4; q++) {
                    dacc[i][q] += (double)acc[i][q];
                    acc[i][q] = 0.f;
                }
        }
        __syncthreads();
    }
    float4 bb = ((const float4*)bnode)[tx];
    #pragma unroll
    for (int i = 0; i < 4; i++) {
        int row = m0 + ty * 4 + i;
        *(float4*)(g_pre + (size_t)row * DD + tx * 4) = make_float4(
            (float)(dacc[i][0] + (double)bb.x), (float)(dacc[i][1] + (double)bb.y),
            (float)(dacc[i][2] + (double)bb.z), (float)(dacc[i][3] + (double)bb.w));
    }
}

// ---------------------------------------------------------------------------
// Kernel 2b: node tail: LN in double (verbatim) + GELU with fp32 erff on a
// double-computed argument (removes the 450us double-erf bottleneck; node
// error rises ~0.5 -> ~2 ulp, same order as the reference's own fp32 noise).
// ---------------------------------------------------------------------------
__global__ void node_tail_kernel(const float* __restrict__ ln_g, const float* __restrict__ ln_b,
                                 float* __restrict__ nodes_out) {
    int wip = threadIdx.x >> 5;
    int lane = threadIdx.x & 31;
    int row = blockIdx.x * 8 + wip;
    if (row >= M_NODES) return;
    double x[4];
    double s = 0.0;
    #pragma unroll
    for (int q = 0; q < 4; q++) {
        x[q] = (double)g_pre[(size_t)row * DD + lane + 32 * q];
        s += x[q];
    }
    #pragma unroll
    for (int o = 16; o > 0; o >>= 1) s += __shfl_xor_sync(~0u, s, o);
    double mu = s * (1.0 / 128.0);
    double vs = 0.0;
    #pragma unroll
    for (int q = 0; q < 4; q++) { double d = x[q] - mu; vs += d * d; }
    #pragma unroll
    for (int o = 16; o > 0; o >>= 1) vs += __shfl_xor_sync(~0u, vs, o);
    double rs = 1.0 / sqrt(vs * (1.0 / 128.0) + 1e-5);
    float yf[4];
    double ssd = 0.0;
    #pragma unroll
    for (int q = 0; q < 4; q++) {
        int d = lane + 32 * q;
        double y = (x[q] - mu) * rs * (double)ln_g[d] + (double)ln_b[d];
        float earg = (float)(y * 0.7071067811865475244);
        double g = 0.5 * y * (1.0 + (double)erff(earg));
        yf[q] = (float)g;
        nodes_out[(size_t)row * DD + d] = yf[q];
        ssd += (double)yf[q] * yf[q];
    }
    #pragma unroll
    for (int o = 16; o > 0; o >>= 1) ssd += __shfl_xor_sync(~0u, ssd, o);
    double dinv = 1.0 / fmax(sqrt(ssd), 1e-12);
    if (lane == 0) g_dinv[row] = dinv;
    float inv = (float)dinv;
    #pragma unroll
    for (int q = 0; q < 4; q++)
        g_nrm[(size_t)row * DD + lane + 32 * q] = yf[q] * inv;
}

// ---------------------------------------------------------------------------
// Kernel 4: sim = nrm @ nrm^T per batch. 32x32 tile, 64 threads, 4x4 micro,
// f32x2 packed FMA.
// ---------------------------------------------------------------------------
__global__ void sim_kernel() {
    __shared__ float As[32][36];
    __shared__ float Bs[32][36];
    int tid = threadIdx.x;
    const float* base = g_nrm + (size_t)blockIdx.z * (NN * DD);
    int by = blockIdx.y, bx = blockIdx.x;
    int tx = tid & 7, ty = tid >> 3;
    u64 acc2[2][4] = {};
    for (int k0 = 0; k0 < 128; k0 += 32) {
        #pragma unroll
        for (int it = 0; it < 4; it++) {
            int idx = tid + it * 64;
            int r = idx >> 3, kg = (idx & 7) * 4;
            int na = by * 32 + r;
            float4 v = (na < NN) ? *(const float4*)(base + (size_t)na * DD + k0 + kg)
                                 : make_float4(0.f, 0.f, 0.f, 0.f);
            As[kg + 0][r] = v.x; As[kg + 1][r] = v.y; As[kg + 2][r] = v.z; As[kg + 3][r] = v.w;
            int ma = bx * 32 + r;
            float4 u = (ma < NN) ? *(const float4*)(base + (size_t)ma * DD + k0 + kg)
                                 : make_float4(0.f, 0.f, 0.f, 0.f);
            Bs[kg + 0][r] = u.x; Bs[kg + 1][r] = u.y; Bs[kg + 2][r] = u.z; Bs[kg + 3][r] = u.w;
        }
        __syncthreads();
        #pragma unroll
        for (int k = 0; k < 32; k++) {
            ulonglong2 av = *(const ulonglong2*)&As[k][ty * 4];
            u64 ap[2] = {av.x, av.y};
            float4 b = *(float4*)&Bs[k][tx * 4];
            u64 b2[4] = {pack2(b.x), pack2(b.y), pack2(b.z), pack2(b.w)};
            #pragma unroll
            for (int p = 0; p < 2; p++)
                #pragma unroll
                for (int j = 0; j < 4; j++) fma2(acc2[p][j], ap[p], b2[j]);
        }
        __syncthreads();
    }
    float accf[4][4];
    #pragma unroll
    for (int p = 0; p < 2; p++)
        #pragma unroll
        for (int j = 0; j < 4; j++) {
            float2 v = unpack2(acc2[p][j]);
            accf[2 * p][j] = v.x;
            accf[2 * p + 1][j] = v.y;
        }
    float* simb = g_sim + (size_t)blockIdx.z * (NN * NN);
    #pragma unroll
    for (int i = 0; i < 4; i++) {
        int n0 = by * 32 + ty * 4 + i;
        if (n0 >= NN) break;
        int mcol = bx * 32 + tx * 4;
        if (mcol + 3 < NN) {
            *(float4*)(simb + n0 * NN + mcol) =
                make_float4(accf[i][0], accf[i][1], accf[i][2], accf[i][3]);
        } else {
            #pragma unroll
            for (int j = 0; j < 4; j++)
                if (mcol + j < NN) simb[n0 * NN + mcol + j] = accf[i][j];
        }
    }
}

// ---------------------------------------------------------------------------
// Kernel 5a: top-16 candidates, one WARP per row (register sort + warp argmax).
// ---------------------------------------------------------------------------
__global__ void cand_kernel() {
    int w = (blockIdx.x * blockDim.x + threadIdx.x) >> 5;
    int lane = threadIdx.x & 31;
    if (w >= M_NODES) return;
    int b = w / NN, n = w % NN;
    const float* row = g_sim + (size_t)b * (NN * NN) + n * NN;

    float v0, v1, v2, v3, v4, v5, v6;
    int   i0, i1, i2, i3, i4, i5, i6;
    {
        int m;
        m = lane;        i0 = m; v0 = (m != n) ? row[m] : -1e38f;
        m = lane + 32;   i1 = m; v1 = (m != n) ? row[m] : -1e38f;
        m = lane + 64;   i2 = m; v2 = (m != n) ? row[m] : -1e38f;
        m = lane + 96;   i3 = m; v3 = (m != n) ? row[m] : -1e38f;
        m = lane + 128;  i4 = m; v4 = (m != n) ? row[m] : -1e38f;
        m = lane + 160;  i5 = m; v5 = (m != n) ? row[m] : -1e38f;
        m = lane + 192;  i6 = m; v6 = (m < NN && m != n) ? row[m] : -1e38f;
    }
    #define CSWP(va, ia, vb, ib)                                             \
        { bool sw = (va < vb) || (va == vb && ia > ib);                      \
          float tv = sw ? vb : va; vb = sw ? va : vb; va = tv;               \
          int ti = sw ? ib : ia;   ib = sw ? ia : ib; ia = ti; }
    #pragma unroll
    for (int rnd = 0; rnd < 4; rnd++) {
        CSWP(v0, i0, v1, i1); CSWP(v2, i2, v3, i3); CSWP(v4, i4, v5, i5);
        if (rnd < 3) { CSWP(v1, i1, v2, i2); CSWP(v3, i3, v4, i4); CSWP(v5, i5, v6, i6); }
    }
    #undef CSWP

    int res = 0;
    #pragma unroll
    for (int k = 0; k < NC; k++) {
        float bv = v0; int bi = i0, bl = lane;
        #pragma unroll
        for (int o = 16; o > 0; o >>= 1) {
            float ov = __shfl_xor_sync(~0u, bv, o);
            int   oi = __shfl_xor_sync(~0u, bi, o);
            int   ol = __shfl_xor_sync(~0u, bl, o);
            bool take = (ov > bv) || (ov == bv && oi < bi);
            bv = take ? ov : bv; bi = take ? oi : bi; bl = take ? ol : bl;
        }
        if (lane == bl) {
            v0 = v1; i0 = i1; v1 = v2; i1 = i2; v2 = v3; i2 = i3;
            v3 = v4; i3 = i4; v4 = v5; i4 = i5; v5 = v6; i5 = i6;
            v6 = -1e38f;
        }
        if (lane == k) res = bi;
    }
    if (lane < NC) g_cand[w * NC + lane] = res;
}

// ---------------------------------------------------------------------------
// Kernel 5b: exact re-rank in double; fp32 round; stable sort; emit top-8.
// ---------------------------------------------------------------------------
__global__ void refine_kernel(const float* __restrict__ nodes, float* __restrict__ adj_out) {
    __shared__ float skey[8][NC];
    __shared__ int   sidx[8][NC];
    int wip = threadIdx.x >> 5;
    int lane = threadIdx.x & 31;
    int t = blockIdx.x * 8 + wip;
    if (t >= M_NODES) return;
    int b = t / NN;
    int rowbase = b * NN;
    double dinv_n = g_dinv[t];
    float4 av = ((const float4*)(nodes + (size_t)t * DD))[lane];
    int myc = (lane < NC) ? g_cand[t * NC + lane] : 0;
    #pragma unroll
    for (int c = 0; c < NC; c++) {
        int j = __shfl_sync(~0u, myc, c);
        float4 bv = ((const float4*)(nodes + (size_t)(rowbase + j) * DD))[lane];
        double p = (double)av.x * bv.x + (double)av.y * bv.y
                 + (double)av.z * bv.z + (double)av.w * bv.w;
        #pragma unroll
        for (int o = 16; o > 0; o >>= 1) p += __shfl_xor_sync(~0u, p, o);
        if (lane == c) {
            double sim = p * dinv_n * g_dinv[rowbase + j];
            skey[wip][c] = (float)sim;
            sidx[wip][c] = j;
        }
    }
    __syncwarp();
    if (lane == 0) {
        float kv[NC]; int ki[NC];
        #pragma unroll
        for (int i = 0; i < NC; i++) { kv[i] = skey[wip][i]; ki[i] = sidx[wip][i]; }
        #pragma unroll
        for (int i = 1; i < NC; i++) {
            float v = kv[i]; int id = ki[i];
            int p = i - 1;
            while (p >= 0 && (kv[p] < v || (kv[p] == v && ki[p] > id))) {
                kv[p + 1] = kv[p]; ki[p + 1] = ki[p]; p--;
            }
            kv[p + 1] = v; ki[p + 1] = id;
        }
        #pragma unroll
        for (int k = 0; k < TK; k++) {
            g_adj[t * TK + k] = ki[k];
            adj_out[t * TK + k] = (float)ki[k];
        }
    }
}

// ---------------------------------------------------------------------------
// Kernel 6: C{1,2} = nodes @ We1[seg*128 : seg*128+128].
// 64x128 tile, 256 threads, 8x4 micro, scalar FFMA.
// ---------------------------------------------------------------------------
__global__ void cgemm64_kernel(const float* __restrict__ nodes, const float* __restrict__ We1) {
    __shared__ float As[32][68];
    __shared__ float4 Bs[1024];
    int tid = threadIdx.x;
    int m0 = blockIdx.x * 64;
    int seg = blockIdx.y;
    float* C = seg ? g_c2 : g_c1;
    const float* W = We1 + (size_t)seg * 128 * DD;
    int tx = tid & 31, ty = tid >> 5;
    float acc[8][4] = {};
    for (int k0 = 0; k0 < 128; k0 += 32) {
        {
            int r = tid >> 2, cb = (tid & 3) * 8;
            const float4* p = (const float4*)(nodes + (size_t)(m0 + r) * DD + k0 + cb);
            float4 v0 = p[0], v1 = p[1];
            As[cb + 0][r] = v0.x; As[cb + 1][r] = v0.y; As[cb + 2][r] = v0.z; As[cb + 3][r] = v0.w;
            As[cb + 4][r] = v1.x; As[cb + 5][r] = v1.y; As[cb + 6][r] = v1.z; As[cb + 7][r] = v1.w;
        }
        {
            const float4* Wg = (const float4*)(W + k0 * DD);
            #pragma unroll
            for (int i = 0; i < 4; i++) Bs[tid + i * 256] = Wg[tid + i * 256];
        }
        __syncthreads();
        #pragma unroll
        for (int cc = 0; cc < 32; cc++) {
            float4 bv = Bs[cc * 32 + tx];
            float4 a0 = *(float4*)&As[cc][ty * 8];
            float4 a1 = *(float4*)&As[cc][ty * 8 + 4];
            float ar[8] = {a0.x, a0.y, a0.z, a0.w, a1.x, a1.y, a1.z, a1.w};
            #pragma unroll
            for (int i = 0; i < 8; i++) {
                acc[i][0] += ar[i] * bv.x; acc[i][1] += ar[i] * bv.y;
                acc[i][2] += ar[i] * bv.z; acc[i][3] += ar[i] * bv.w;
            }
        }
        __syncthreads();
    }
    #pragma unroll
    for (int i = 0; i < 8; i++) {
        int row = m0 + ty * 8 + i;
        ((float4*)(C + (size_t)row * DD))[tx] =
            make_float4(acc[i][0], acc[i][1], acc[i][2], acc[i][3]);
    }
}

// ---------------------------------------------------------------------------
// Kernel 7: C3 = table @ We1[256:384] + be1 (729 rows, tiny).
// ---------------------------------------------------------------------------
__global__ void c3_kernel(const float* __restrict__ We1, const float* __restrict__ be1) {
    __shared__ float ts[128];
    int row = blockIdx.x, t = threadIdx.x;
    ts[t] = g_table[row * DD + t];
    __syncthreads();
    float acc = be1[t];
    const float* W = We1 + (size_t)256 * DD;
    #pragma unroll 8
    for (int k = 0; k < 128; k++) acc += ts[k] * W[k * DD + t];
    g_c3[row * DD + t] = acc;
}

// ---------------------------------------------------------------------------
// Kernel 8: edges = GELU(C1[n] + C2[adj] + C3[disp]) @ We2 + be2.
// Double-buffered 64x128 tile, 8x4 micro (1519.7-best version).
// ---------------------------------------------------------------------------
__global__ void edge_fused64_kernel(const float* __restrict__ We2, const float* __restrict__ be2,
                                    float* __restrict__ edges_out) {
    __shared__ float As[2][32][68];
    __shared__ float4 Bs[2][1024];
    __shared__ int s1[64], s2[64], s3[64];
    int tid = threadIdx.x;
    int m0 = blockIdx.x * 64;
    if (tid < 64) {
        int e = m0 + tid;
        int bn = e >> 3;
        int b = bn / NN, n = bn - b * NN;
        int j = g_adj[e];
        s1[tid] = bn * DD;
        s2[tid] = (b * NN + j) * DD;
        int rn = n / 14, cn = n % 14, rj = j / 14, cj = j % 14;
        s3[tid] = ((rj - rn + 13) * 27 + (cj - cn + 13)) * DD;
    }
    __syncthreads();
    int tx = tid & 31, ty = tid >> 5;
    int gr = tid >> 2, gc = (tid & 3) * 8;
    float acc[8][4] = {};

    {
        const float* p1 = g_c1 + s1[gr] + gc;
        const float* p2 = g_c2 + s2[gr] + gc;
        const float* p3 = g_c3 + s3[gr] + gc;
        #pragma unroll
        for (int q = 0; q < 2; q++) {
            float4 v1 = *(const float4*)(p1 + q * 4);
            float4 v2 = *(const float4*)(p2 + q * 4);
            float4 v3 = *(const float4*)(p3 + q * 4);
            As[0][gc + q * 4 + 0][gr] = gelu_exact(v1.x + v2.x + v3.x);
            As[0][gc + q * 4 + 1][gr] = gelu_exact(v1.y + v2.y + v3.y);
            As[0][gc + q * 4 + 2][gr] = gelu_exact(v1.z + v2.z + v3.z);
            As[0][gc + q * 4 + 3][gr] = gelu_exact(v1.w + v2.w + v3.w);
        }
        const float4* Wg = (const float4*)We2;
        #pragma unroll
        for (int i = 0; i < 4; i++) Bs[0][tid + i * 256] = Wg[tid + i * 256];
    }
    __syncthreads();

    #pragma unroll
    for (int c = 0; c < 4; c++) {
        int buf = c & 1;
        float4 pre[6], bpre[4];
        if (c < 3) {
            int kn = (c + 1) * 32;
            const float* p1 = g_c1 + s1[gr] + kn + gc;
            const float* p2 = g_c2 + s2[gr] + kn + gc;
            const float* p3 = g_c3 + s3[gr] + kn + gc;
            pre[0] = *(const float4*)(p1);     pre[1] = *(const float4*)(p1 + 4);
            pre[2] = *(const float4*)(p2);     pre[3] = *(const float4*)(p2 + 4);
            pre[4] = *(const float4*)(p3);     pre[5] = *(const float4*)(p3 + 4);
            const float4* Wg = (const float4*)(We2 + kn * DD);
            #pragma unroll
            for (int i = 0; i < 4; i++) bpre[i] = Wg[tid + i * 256];
        }
        #pragma unroll
        for (int cc = 0; cc < 32; cc++) {
            float4 bv = Bs[buf][cc * 32 + tx];
            float4 a0 = *(float4*)&As[buf][cc][ty * 8];
            float4 a1 = *(float4*)&As[buf][cc][ty * 8 + 4];
            float ar[8] = {a0.x, a0.y, a0.z, a0.w, a1.x, a1.y, a1.z, a1.w};
            #pragma unroll
            for (int i = 0; i < 8; i++) {
                acc[i][0] += ar[i] * bv.x; acc[i][1] += ar[i] * bv.y;
                acc[i][2] += ar[i] * bv.z; acc[i][3] += ar[i] * bv.w;
            }
        }
        if (c < 3) {
            int nb = buf ^ 1;
            #pragma unroll
            for (int q = 0; q < 2; q++) {
                float4 v1 = pre[q], v2 = pre[2 + q], v3 = pre[4 + q];
                As[nb][gc + q * 4 + 0][gr] = gelu_exact(v1.x + v2.x + v3.x);
                As[nb][gc + q * 4 + 1][gr] = gelu_exact(v1.y + v2.y + v3.y);
                As[nb][gc + q * 4 + 2][gr] = gelu_exact(v1.z + v2.z + v3.z);
                As[nb][gc + q * 4 + 3][gr] = gelu_exact(v1.w + v2.w + v3.w);
            }
            #pragma unroll
            for (int i = 0; i < 4; i++) Bs[nb][tid + i * 256] = bpre[i];
        }
        __syncthreads();
    }

    float4 bb = ((const float4*)be2)[tx];
    #pragma unroll
    for (int i = 0; i < 8; i++) {
        int row = m0 + ty * 8 + i;
        ((float4*)(edges_out + (size_t)row * DD))[tx] =
            make_float4(acc[i][0] + bb.x, acc[i][1] + bb.y,
                        acc[i][2] + bb.z, acc[i][3] + bb.w);
    }
}

// ---------------------------------------------------------------------------
extern "C" void kernel_launch(void* const* d_in, const int* in_sizes, int n_in,
                              void* d_out, int out_size) {
    const float* feat = (const float*)d_in[0];
    const float* Wn   = (const float*)d_in[1];
    const float* bn   = (const float*)d_in[2];
    const float* lng  = (const float*)d_in[3];
    const float* lnb  = (const float*)d_in[4];
    const float* Wp1  = (const float*)d_in[5];
    const float* bp1  = (const float*)d_in[6];
    const float* Wp2  = (const float*)d_in[7];
    const float* bp2  = (const float*)d_in[8];
    const float* We1  = (const float*)d_in[9];
    const float* be1  = (const float*)d_in[10];
    const float* We2  = (const float*)d_in[11];
    const float* be2  = (const float*)d_in[12];

    float* out = (float*)d_out;
    float* nodes_out = out;                                   // B*N*D
    float* edges_out = out + (size_t)M_NODES * DD;            // B*N*K*D
    float* adj_out   = edges_out + (size_t)NE * DD;           // B*N*K

    // node_tail now occupies ncu's captured slot (#4) for verification.
    pos_a_kernel<<<729, 64>>>(Wp1, bp1);
    pos_b_kernel<<<729, 128>>>(Wp2, bp2);
    node_gemm_kernel<<<M_NODES / 32, 256>>>(feat, Wn, bn);
    node_tail_kernel<<<M_NODES / 8, 256>>>(lng, lnb, nodes_out);
    sim_kernel<<<dim3(7, 7, BB), 64>>>();
    cand_kernel<<<(M_NODES * 32 + 255) / 256, 256>>>();
    refine_kernel<<<(M_NODES + 7) / 8, 256>>>(nodes_out, adj_out);
    cgemm64_kernel<<<dim3(M_NODES / 64, 2), 256>>>(nodes_out, We1);
    c3_kernel<<<729, 128>>>(We1, be1);
    edge_fused64_kernel<<<NE / 64, 256>>>(We2, be2, edges_out);
}